// round 15
// baseline (speedup 1.0000x reference)
#include <cuda_runtime.h>
#include <cuda_fp16.h>
#include <mma.h>
#include <math.h>
#include <stdint.h>

using namespace nvcuda;

#define NN 4096
#define DD 256
#define HH 4
#define DHH 64
#define EE 65536
#define NW 128
#define LNEPS 1e-5f

// ---------------- device scratch ----------------
__device__ int      g_is64;
__device__ unsigned g_A   [NN*NW];
__device__ unsigned g_ML  [NN*NW];
__device__ unsigned g_UND [NN*NW];
__device__ unsigned g_UNDT[NN*NW];
__device__ unsigned g_MM  [NN*NW];

__device__ __half g_zh  [3L*NN*HH*DD];
__device__ __half g_xh  [NN*DD];
__device__ __half g_wh  [3*HH*DD*DD + 4*DD*DD + DD*3*DD];
__device__ __half g_P   [4L*NN*NN];
__device__ float  g_den [HH*NN];
__device__ float  g_part [HH*NN*DD];
__device__ float  g_part2[HH*NN*DD];
__device__ unsigned g_maxu[HH];

__device__ float g_ssrc[3*HH*NN];
__device__ float g_F1  [3*HH*NN];
__device__ float g_F2  [3*HH*NN];
__device__ float g_T   [3*HH*NN];
__device__ float g_E1  [3*HH*NN];
__device__ float g_E2  [3*HH*NN];

__device__ __half g_cath[NN*3*DD];
__device__ float g_sorted[HH*NN];
__device__ int   g_perm  [HH*NN];
__device__ float g_P1[HH*NN*DD];
__device__ float g_P2[HH*NN*DD];
__device__ float g_C1[HH*NN];
__device__ float g_C2[HH*NN];
__device__ float g_T1[HH*32*DD], g_T2[HH*32*DD];
__device__ float g_O1[HH*33*DD], g_O2[HH*33*DD];
__device__ float g_TC1[HH*32], g_TC2[HH*32];
__device__ float g_OC1[HH*33], g_OC2[HH*33];

__device__ float  g_q   [NN*DD];
__device__ float  g_k3  [3*NN*DD];
__device__ float  g_v3  [3*NN*DD];
__device__ __half g_atth[NN*DD];
__device__ float  g_xatt[NN*DD];
__device__ float  g_hbuf[NN*DD];

#define WOFF_L  0
#define WOFF_M  262144
#define WOFF_G  524288
#define WOFF_Q  786432
#define WOFF_K  851968
#define WOFF_V  917504
#define WOFF_O  983040
#define WOFF_F  1048576
#define WTOT    1245184

__device__ __forceinline__ unsigned fkey(float f) {
    unsigned u = __float_as_uint(f);
    return (u >> 31) ? ~u : (u | 0x80000000u);
}
__device__ __forceinline__ float fdec(unsigned k) {
    unsigned u = (k >> 31) ? (k & 0x7fffffffu) : ~k;
    return __uint_as_float(u);
}

__device__ __forceinline__ void cp16(uint32_t dst, const void* src) {
    asm volatile("cp.async.cg.shared.global [%0], [%1], 16;" :: "r"(dst), "l"(src));
}
#define CP_COMMIT() asm volatile("cp.async.commit_group;" ::: "memory")
#define CP_WAIT0()  asm volatile("cp.async.wait_group 0;" ::: "memory")

// ---------------- setup kernels ----------------
__global__ void k_detect(const unsigned* e) {
    if (threadIdx.x == 0) {
        int all0 = 1;
        for (int i = 0; i < 128; i++) if (e[2*i+1] != 0u) { all0 = 0; break; }
        g_is64 = all0;
    }
}

__global__ void k_clear() {
    int i = blockIdx.x * blockDim.x + threadIdx.x;
    if (i < NN*NW) { g_A[i] = 0u; g_ML[i] = 0u; }
}

__global__ void k_edges(const int* e) {
    int i = blockIdx.x * blockDim.x + threadIdx.x;
    if (i >= EE) return;
    int s, t;
    if (g_is64) { s = e[2*i]; t = e[2*(EE+i)]; }
    else        { s = e[i];   t = e[EE+i];     }
    atomicOr(&g_A [s*NW + (t>>5)], 1u << (t & 31));
    atomicOr(&g_ML[t*NW + (s>>5)], 1u << (s & 31));
}

__global__ void k_eye_ml() {
    int i = blockIdx.x * blockDim.x + threadIdx.x;
    if (i < NN) g_ML[i*NW + (i>>5)] |= 1u << (i & 31);
}

__global__ void k_twohop() {
    int i = blockIdx.x, w = threadIdx.x;
    __shared__ unsigned sh[NW];
    sh[w] = g_A[i*NW + w];
    __syncthreads();
    unsigned acc = sh[w];
    for (int w2 = 0; w2 < NW; w2++) {
        unsigned bits = sh[w2];
        while (bits) {
            int b = __ffs(bits) - 1; bits &= bits - 1;
            acc |= g_A[((w2<<5)+b)*NW + w];
        }
    }
    g_UND[i*NW + w] = acc;
}

__global__ void k_transpose() {
    int tile = blockIdx.x * 8 + (threadIdx.x >> 5);
    int lane = threadIdx.x & 31;
    int ti = tile >> 7, tj = tile & 127;
    __shared__ unsigned sm[8][32];
    int wslot = threadIdx.x >> 5;
    sm[wslot][lane] = g_UND[(ti*32 + lane)*NW + tj];
    __syncwarp();
    unsigned y = 0;
    #pragma unroll
    for (int b = 0; b < 32; b++) y |= ((sm[wslot][b] >> lane) & 1u) << b;
    g_UNDT[(tj*32 + lane)*NW + ti] = y;
}

__global__ void k_mm() {
    int i = blockIdx.x, w = threadIdx.x;
    unsigned res = g_UND[i*NW + w] | g_UNDT[i*NW + w];
    if (w == (i >> 5)) res |= 1u << (i & 31);
    g_MM[i*NW + w] = res;
}

__global__ void k_conv(const float* __restrict__ x,
                       const float* Wl, const float* Wm, const float* Wg,
                       const float* Wq, const float* Wk, const float* Wv,
                       const float* Wo, const float* Wf) {
    int i = blockIdx.x * blockDim.x + threadIdx.x;
    if (i < 4) g_maxu[i] = 0u;
    if (i < NN*DD) g_xh[i] = __float2half(x[i]);
    if (i < WTOT) {
        float v;
        if      (i < WOFF_M) v = Wl[i - WOFF_L];
        else if (i < WOFF_G) v = Wm[i - WOFF_M];
        else if (i < WOFF_Q) v = Wg[i - WOFF_G];
        else if (i < WOFF_K) v = Wq[i - WOFF_Q];
        else if (i < WOFF_V) v = Wk[i - WOFF_K];
        else if (i < WOFF_O) v = Wv[i - WOFF_V];
        else if (i < WOFF_F) v = Wo[i - WOFF_O];
        else                 v = Wf[i - WOFF_F];
        g_wh[i] = __float2half(v);
    }
}

// ---------------- 128x128 double-buffered wmma GEMM (projections) ----------------
__global__ __launch_bounds__(256, 2)
void k_hgemm2(const __half* __restrict__ A, int lda, long sA,
              const __half* __restrict__ B, int ldb, long sB, int brm,
              const float* __restrict__ bias,
              float* __restrict__ Cf, int ldc, long sC,
              __half* Ch, int ldch, long sCh, int K) {
    int bz = blockIdx.z;
    const __half* Ae = A + (long)bz * sA;
    const __half* Be = B + (long)bz * sB;
    float* cf = Cf ? Cf + (long)bz * sC : (float*)0;
    __half* ch = Ch ? Ch + (long)bz * sCh : (__half*)0;
    int bm = blockIdx.y << 7;
    int bn = blockIdx.x << 7;
    int tid = threadIdx.x;
    int wid = tid >> 5, lane = tid & 31;
    int wm = wid >> 2, wn = wid & 3;

    __shared__ __half As[2][5120];
    __shared__ __half Bs[2][5120];

    wmma::fragment<wmma::accumulator,16,16,16,float> acc[4][2];
    #pragma unroll
    for (int i = 0; i < 4; i++)
        #pragma unroll
        for (int j = 0; j < 2; j++) wmma::fill_fragment(acc[i][j], 0.f);

    int KT = K >> 5;
    int i0 = tid*2, i1 = tid*2 + 1;

    {
        int r0 = i0>>2, s0 = i0&3, r1 = i1>>2, s1 = i1&3;
        *(uint4*)&As[0][r0*40 + s0*8] = *(const uint4*)&Ae[(long)(bm+r0)*lda + s0*8];
        *(uint4*)&As[0][r1*40 + s1*8] = *(const uint4*)&Ae[(long)(bm+r1)*lda + s1*8];
        if (brm) {
            int br0 = i0>>4, bs0 = i0&15, br1 = i1>>4, bs1 = i1&15;
            *(uint4*)&Bs[0][br0*144 + bs0*8] = *(const uint4*)&Be[(long)br0*ldb + bn + bs0*8];
            *(uint4*)&Bs[0][br1*144 + bs1*8] = *(const uint4*)&Be[(long)br1*ldb + bn + bs1*8];
        } else {
            *(uint4*)&Bs[0][r0*40 + s0*8] = *(const uint4*)&Be[(long)(bn+r0)*ldb + s0*8];
            *(uint4*)&Bs[0][r1*40 + s1*8] = *(const uint4*)&Be[(long)(bn+r1)*ldb + s1*8];
        }
    }
    __syncthreads();

    int buf = 0;
    for (int kt = 0; kt < KT; kt++) {
        uint4 pa0, pa1, pb0, pb1;
        int havenext = (kt + 1 < KT);
        int k0n = (kt + 1) << 5;
        int r0 = i0>>2, s0 = i0&3, r1 = i1>>2, s1 = i1&3;
        int br0 = i0>>4, bs0 = i0&15, br1 = i1>>4, bs1 = i1&15;
        if (havenext) {
            pa0 = *(const uint4*)&Ae[(long)(bm+r0)*lda + k0n + s0*8];
            pa1 = *(const uint4*)&Ae[(long)(bm+r1)*lda + k0n + s1*8];
            if (brm) {
                pb0 = *(const uint4*)&Be[(long)(k0n+br0)*ldb + bn + bs0*8];
                pb1 = *(const uint4*)&Be[(long)(k0n+br1)*ldb + bn + bs1*8];
            } else {
                pb0 = *(const uint4*)&Be[(long)(bn+r0)*ldb + k0n + s0*8];
                pb1 = *(const uint4*)&Be[(long)(bn+r1)*ldb + k0n + s1*8];
            }
        }
        #pragma unroll
        for (int kk = 0; kk < 2; kk++) {
            wmma::fragment<wmma::matrix_a,16,16,16,__half,wmma::row_major> af[4];
            #pragma unroll
            for (int i = 0; i < 4; i++)
                wmma::load_matrix_sync(af[i], &As[buf][(wm*64 + i*16)*40 + kk*16], 40);
            if (brm) {
                wmma::fragment<wmma::matrix_b,16,16,16,__half,wmma::row_major> bf[2];
                #pragma unroll
                for (int j = 0; j < 2; j++)
                    wmma::load_matrix_sync(bf[j], &Bs[buf][kk*16*144 + wn*32 + j*16], 144);
                #pragma unroll
                for (int i = 0; i < 4; i++)
                    #pragma unroll
                    for (int j = 0; j < 2; j++)
                        wmma::mma_sync(acc[i][j], af[i], bf[j], acc[i][j]);
            } else {
                wmma::fragment<wmma::matrix_b,16,16,16,__half,wmma::col_major> bf[2];
                #pragma unroll
                for (int j = 0; j < 2; j++)
                    wmma::load_matrix_sync(bf[j], &Bs[buf][(wn*32 + j*16)*40 + kk*16], 40);
                #pragma unroll
                for (int i = 0; i < 4; i++)
                    #pragma unroll
                    for (int j = 0; j < 2; j++)
                        wmma::mma_sync(acc[i][j], af[i], bf[j], acc[i][j]);
            }
        }
        if (havenext) {
            *(uint4*)&As[buf^1][r0*40 + s0*8] = pa0;
            *(uint4*)&As[buf^1][r1*40 + s1*8] = pa1;
            if (brm) {
                *(uint4*)&Bs[buf^1][br0*144 + bs0*8] = pb0;
                *(uint4*)&Bs[buf^1][br1*144 + bs1*8] = pb1;
            } else {
                *(uint4*)&Bs[buf^1][r0*40 + s0*8] = pb0;
                *(uint4*)&Bs[buf^1][r1*40 + s1*8] = pb1;
            }
        }
        __syncthreads();
        buf ^= 1;
    }

    float* scratch = (float*)&As[0][0] + wid * 320;
    int er = lane >> 1, ec = (lane & 1) * 8;
    #pragma unroll
    for (int i = 0; i < 4; i++) {
        #pragma unroll
        for (int j = 0; j < 2; j++) {
            wmma::store_matrix_sync(scratch, acc[i][j], 20, wmma::mem_row_major);
            __syncwarp();
            int m = bm + wm*64 + i*16 + er;
            int n = bn + wn*32 + j*16 + ec;
            float4 v0 = *(float4*)&scratch[er*20 + ec];
            float4 v1 = *(float4*)&scratch[er*20 + ec + 4];
            if (bias) {
                v0.x += bias[n];   v0.y += bias[n+1]; v0.z += bias[n+2]; v0.w += bias[n+3];
                v1.x += bias[n+4]; v1.y += bias[n+5]; v1.z += bias[n+6]; v1.w += bias[n+7];
            }
            if (cf) {
                *(float4*)&cf[(long)m*ldc + n]     = v0;
                *(float4*)&cf[(long)m*ldc + n + 4] = v1;
            }
            if (ch) {
                __half2 h0 = __floats2half2_rn(v0.x, v0.y);
                __half2 h1 = __floats2half2_rn(v0.z, v0.w);
                __half2 h2 = __floats2half2_rn(v1.x, v1.y);
                __half2 h3 = __floats2half2_rn(v1.z, v1.w);
                uint4 pk;
                pk.x = *(unsigned*)&h0; pk.y = *(unsigned*)&h1;
                pk.z = *(unsigned*)&h2; pk.w = *(unsigned*)&h3;
                *(uint4*)&ch[(long)m*ldch + n] = pk;
            }
            __syncwarp();
        }
    }
}

// ---------------- P@z GEMM: R12 version + row-range offset ----------------
// grid (2, 32, 8): bn (128 cols), bm (64 rows within half), bz = head*2 + ks.
__global__ __launch_bounds__(128)
void k_pgemm(int rbase) {
    int bz = blockIdx.z;
    int h  = bz >> 1;
    int ks = bz & 1;
    int koff = ks << 11;
    const __half* Ae = g_P + (long)h*NN*NN;
    const __half* Be = g_zh + (long)NN*1024 + h*256;
    float* cf = (ks ? g_part2 : g_part) + (long)h*NN*DD;
    int bm = rbase + (blockIdx.y << 6);
    int bn = blockIdx.x << 7;
    int tid = threadIdx.x;
    int wid = tid >> 5, lane = tid & 31;

    __shared__ __half As[2][64*40];
    __shared__ __half Bs[2][32*136];

    wmma::fragment<wmma::accumulator,16,16,16,float> acc[4][2];
    #pragma unroll
    for (int i = 0; i < 4; i++)
        #pragma unroll
        for (int j = 0; j < 2; j++) wmma::fill_fragment(acc[i][j], 0.f);

    int ua0 = tid*2, ua1 = tid*2 + 1;
    int ar0 = ua0 >> 2, as0 = ua0 & 3, ar1 = ua1 >> 2, as1 = ua1 & 3;

    {
        int k0 = koff;
        cp16((uint32_t)__cvta_generic_to_shared(&As[0][ar0*40 + as0*8]),
             &Ae[(long)(bm+ar0)*NN + k0 + as0*8]);
        cp16((uint32_t)__cvta_generic_to_shared(&As[0][ar1*40 + as1*8]),
             &Ae[(long)(bm+ar1)*NN + k0 + as1*8]);
        #pragma unroll
        for (int t = 0; t < 4; t++) {
            int u = tid*4 + t;
            int br = u >> 4, bs = u & 15;
            cp16((uint32_t)__cvta_generic_to_shared(&Bs[0][br*136 + bs*8]),
                 &Be[(long)(k0+br)*1024 + bn + bs*8]);
        }
        CP_COMMIT();
        CP_WAIT0();
    }
    __syncthreads();

    int buf = 0;
    for (int kt = 0; kt < 64; kt++) {
        if (kt + 1 < 64) {
            int k0 = koff + ((kt + 1) << 5);
            cp16((uint32_t)__cvta_generic_to_shared(&As[buf^1][ar0*40 + as0*8]),
                 &Ae[(long)(bm+ar0)*NN + k0 + as0*8]);
            cp16((uint32_t)__cvta_generic_to_shared(&As[buf^1][ar1*40 + as1*8]),
                 &Ae[(long)(bm+ar1)*NN + k0 + as1*8]);
            #pragma unroll
            for (int t = 0; t < 4; t++) {
                int u = tid*4 + t;
                int br = u >> 4, bs = u & 15;
                cp16((uint32_t)__cvta_generic_to_shared(&Bs[buf^1][br*136 + bs*8]),
                     &Be[(long)(k0+br)*1024 + bn + bs*8]);
            }
            CP_COMMIT();
        }
        #pragma unroll
        for (int kk = 0; kk < 2; kk++) {
            wmma::fragment<wmma::matrix_a,16,16,16,__half,wmma::row_major> af[4];
            #pragma unroll
            for (int i = 0; i < 4; i++)
                wmma::load_matrix_sync(af[i], &As[buf][(i*16)*40 + kk*16], 40);
            wmma::fragment<wmma::matrix_b,16,16,16,__half,wmma::row_major> bf[2];
            #pragma unroll
            for (int j = 0; j < 2; j++)
                wmma::load_matrix_sync(bf[j], &Bs[buf][kk*16*136 + wid*32 + j*16], 136);
            #pragma unroll
            for (int i = 0; i < 4; i++)
                #pragma unroll
                for (int j = 0; j < 2; j++)
                    wmma::mma_sync(acc[i][j], af[i], bf[j], acc[i][j]);
        }
        CP_WAIT0();
        __syncthreads();
        buf ^= 1;
    }

    float* scratch = (float*)&As[0][0] + wid * 320;
    int er = lane >> 1, ec = (lane & 1) * 8;
    #pragma unroll
    for (int i = 0; i < 4; i++) {
        #pragma unroll
        for (int j = 0; j < 2; j++) {
            wmma::store_matrix_sync(scratch, acc[i][j], 20, wmma::mem_row_major);
            __syncwarp();
            int m = bm + i*16 + er;
            int n = bn + wid*32 + j*16 + ec;
            *(float4*)&cf[(long)m*DD + n]     = *(float4*)&scratch[er*20 + ec];
            *(float4*)&cf[(long)m*DD + n + 4] = *(float4*)&scratch[er*20 + ec + 4];
            __syncwarp();
        }
    }
}

// ---------------- attention scalars, per scale ----------------
__global__ void k_scores(int sc, const float* __restrict__ as, const float* __restrict__ ad) {
    int item = blockIdx.x * 8 + (threadIdx.x >> 5);
    int lane = threadIdx.x & 31;
    if (item >= HH*NN) return;
    int n = item & (NN - 1);
    int h = item >> 12;
    int gi = sc*HH*NN + item;
    const __half* zr = g_zh + ((long)sc*NN + n)*1024 + h*DD;
    float s1 = 0.f, s2 = 0.f;
    for (int d0 = lane; d0 < DD; d0 += 32) {
        float zv = __half2float(zr[d0]);
        s1 += zv * as[h*DD + d0];
        s2 += zv * ad[h*DD + d0];
    }
    #pragma unroll
    for (int o = 16; o; o >>= 1) {
        s1 += __shfl_down_sync(0xffffffffu, s1, o);
        s2 += __shfl_down_sync(0xffffffffu, s2, o);
    }
    if (lane == 0) {
        g_ssrc[gi] = s1; g_F1[gi] = expf(s1);  g_F2[gi] = expf(0.2f * s1);
        g_T[gi] = -s2;   g_E1[gi] = expf(s2);  g_E2[gi] = expf(0.2f * s2);
        if (sc == 1) atomicMax(&g_maxu[h], fkey(s1));
    }
}

// ---------------- LOCAL sparse gather ----------------
__global__ void k_agg2(int sc, const unsigned* __restrict__ M,
                       const float* __restrict__ bias,
                       __half* __restrict__ out, int ldo) {
    int i = blockIdx.x, tid = threadIdx.x;
    __shared__ int   s_idx[NN];
    __shared__ float s_w[64][4];
    __shared__ int   s_cntw[NW], s_off[NW + 1];
    __shared__ float s_t[4], s_e1[4], s_e2[4];
    __shared__ float s_acc[2][4][32][8];
    __shared__ float s_den[2][4];
    if (tid < 4) {
        int id = (sc*4 + tid) * NN + i;
        s_t[tid] = g_T[id]; s_e1[tid] = g_E1[id]; s_e2[tid] = g_E2[id];
    }
    if (tid < NW) s_cntw[tid] = __popc(M[i*NW + tid]);
    __syncthreads();
    if (tid == 0) {
        int a = 0;
        for (int w = 0; w < NW; w++) { s_off[w] = a; a += s_cntw[w]; }
        s_off[NW] = a;
    }
    __syncthreads();
    if (tid < NW) {
        unsigned bits = M[i*NW + tid];
        int p = s_off[tid];
        while (bits) { int b = __ffs(bits) - 1; bits &= bits - 1; s_idx[p++] = (tid<<5) + b; }
    }
    __syncthreads();
    int deg = s_off[NW];
    int grp = tid >> 7;
    int t2  = tid & 127;
    int h   = t2 >> 5;
    int slot = t2 & 31;
    const uint4* zh = (const uint4*)(g_zh + (long)sc*NN*1024);
    float acc[8] = {0,0,0,0,0,0,0,0};
    float den = 0.f;
    int jw = tid & 63, hw = tid >> 6;
    for (int base = 0; base < deg; base += 64) {
        int cnt = min(64, deg - base);
        if (jw < cnt) {
            int j = s_idx[base + jw];
            int id = (sc*4 + hw) * NN + j;
            float sj = g_ssrc[id];
            s_w[jw][hw] = (sj > s_t[hw]) ? s_e1[hw] * g_F1[id] : s_e2[hw] * g_F2[id];
        }
        __syncthreads();
        for (int q = grp; q < cnt; q += 2) {
            int j = s_idx[base + q];
            uint4 zv = zh[(long)j * 128 + h*32 + slot];
            float w = s_w[q][h];
            den += w;
            __half2 p0 = *(__half2*)&zv.x, p1 = *(__half2*)&zv.y;
            __half2 p2 = *(__half2*)&zv.z, p3 = *(__half2*)&zv.w;
            float2 f0 = __half22float2(p0), f1 = __half22float2(p1);
            float2 f2 = __half22float2(p2), f3 = __half22float2(p3);
            acc[0] += w*f0.x; acc[1] += w*f0.y;
            acc[2] += w*f1.x; acc[3] += w*f1.y;
            acc[4] += w*f2.x; acc[5] += w*f2.y;
            acc[6] += w*f3.x; acc[7] += w*f3.y;
        }
        __syncthreads();
    }
    #pragma unroll
    for (int k = 0; k < 8; k++) s_acc[grp][h][slot][k] = acc[k];
    if (slot == 0) s_den[grp][h] = den;
    __syncthreads();
    int c = tid;
    float m = 0.f;
    #pragma unroll
    for (int hh2 = 0; hh2 < 4; hh2++) {
        float d = s_den[0][hh2] + s_den[1][hh2];
        float v = s_acc[0][hh2][c>>3][c&7] + s_acc[1][hh2][c>>3][c&7];
        m += v / d;
    }
    out[(long)i * ldo + c] = __float2half(fmaxf(0.25f * m + bias[c], 0.f));
}

// ---------------- MID: dense P build + combine ----------------
__global__ void k_buildP() {
    int grp = blockIdx.x, h = blockIdx.y;
    int tid = threadIdx.x;
    int row0 = grp * 16;
    int base = (4 + h) * NN;
    __shared__ float sf1[256], sf2[256], ssj[256];
    __shared__ unsigned smask[16][8];
    __shared__ float ra[16], rb[16], rt[16];
    __shared__ float sred[256];
    if (tid < 16) {
        int i = row0 + tid;
        float t = g_T[base + i];
        float sdst = -t;
        float m = sdst + fdec(g_maxu[h]);
        m = m > 0.f ? m : 0.2f * m;
        ra[tid] = expf(sdst - m);
        rb[tid] = expf(0.2f * sdst - m);
        rt[tid] = t;
    }
    float dsum[16];
    #pragma unroll
    for (int r = 0; r < 16; r++) dsum[r] = 0.f;
    __syncthreads();
    for (int c0 = 0; c0 < NN; c0 += 256) {
        sf1[tid] = g_F1[base + c0 + tid];
        sf2[tid] = g_F2[base + c0 + tid];
        ssj[tid] = g_ssrc[base + c0 + tid];
        if (tid < 128) smask[tid>>3][tid&7] = g_MM[(row0 + (tid>>3))*NW + (c0>>5) + (tid&7)];
        __syncthreads();
        float f1 = sf1[tid], f2 = sf2[tid], sj = ssj[tid];
        int wd = tid >> 5; unsigned bm = 1u << (tid & 31);
        long pbase = ((long)h*NN + row0)*NN + c0 + tid;
        #pragma unroll
        for (int r = 0; r < 16; r++) {
            float w = 0.f;
            if (smask[r][wd] & bm)
                w = (sj > rt[r]) ? ra[r]*f1 : rb[r]*f2;
            dsum[r] += w;
            g_P[pbase + (long)r*NN] = __float2half(w);
        }
        __syncthreads();
    }
    for (int r = 0; r < 16; r++) {
        sred[tid] = dsum[r]; __syncthreads();
        for (int o = 128; o; o >>= 1) { if (tid < o) sred[tid] += sred[tid+o]; __syncthreads(); }
        if (tid == 0) g_den[h*NN + row0 + r] = sred[0];
        __syncthreads();
    }
}

__global__ void k_midcomb(const float* __restrict__ bias, int rbase) {
    int i = rbase + blockIdx.x, c = threadIdx.x;
    float m = 0.f;
    #pragma unroll
    for (int h = 0; h < 4; h++) {
        long idx = ((long)h*NN + i)*DD + c;
        m += (g_part[idx] + g_part2[idx]) / g_den[h*NN + i];
    }
    g_cath[(long)i*768 + 256 + c] = __float2half(fmaxf(0.25f * m + bias[c], 0.f));
}

// ---------------- global scale ----------------
__global__ void k_sort() {
    int h = blockIdx.x, tid = threadIdx.x;
    __shared__ float key[NN];
    __shared__ int   idx[NN];
    for (int i = tid; i < NN; i += 1024) { key[i] = g_ssrc[(8 + h)*NN + i]; idx[i] = i; }
    __syncthreads();
    for (int k = 2; k <= NN; k <<= 1) {
        for (int j = k >> 1; j > 0; j >>= 1) {
            for (int i = tid; i < NN; i += 1024) {
                int ixj = i ^ j;
                if (ixj > i) {
                    bool up = (i & k) == 0;
                    float a = key[i], b = key[ixj];
                    if ((a > b) == up) {
                        key[i] = b; key[ixj] = a;
                        int t = idx[i]; idx[i] = idx[ixj]; idx[ixj] = t;
                    }
                }
            }
            __syncthreads();
        }
    }
    for (int i = tid; i < NN; i += 1024) { g_sorted[h*NN + i] = key[i]; g_perm[h*NN + i] = idx[i]; }
}

__global__ void k_prefA() {
    int h = blockIdx.x >> 5, k = blockIdx.x & 31;
    int c = threadIdx.x;
    int base = (8 + h) * NN;
    float a1 = 0.f, a2 = 0.f, c1 = 0.f, c2 = 0.f;
    int r0 = k << 7;
    for (int l = 0; l < 128; l++) {
        int r = r0 + l;
        int j = g_perm[h*NN + r];
        float f1 = g_F1[base + j], f2 = g_F2[base + j];
        float zv = __half2float(g_zh[((long)2*NN + j)*1024 + h*DD + c]);
        a1 += f1 * zv; a2 += f2 * zv;
        g_P1[((long)h*NN + r)*DD + c] = a1;
        g_P2[((long)h*NN + r)*DD + c] = a2;
        if (c == 0) { c1 += f1; c2 += f2; g_C1[h*NN + r] = c1; g_C2[h*NN + r] = c2; }
    }
    g_T1[(h*32 + k)*DD + c] = a1;
    g_T2[(h*32 + k)*DD + c] = a2;
    if (c == 0) { g_TC1[h*32 + k] = c1; g_TC2[h*32 + k] = c2; }
}

__global__ void k_prefB() {
    int h = blockIdx.x, c = threadIdx.x;
    float o1 = 0.f, o2 = 0.f;
    for (int k = 0; k < 32; k++) {
        g_O1[(h*33 + k)*DD + c] = o1; g_O2[(h*33 + k)*DD + c] = o2;
        o1 += g_T1[(h*32 + k)*DD + c]; o2 += g_T2[(h*32 + k)*DD + c];
    }
    g_O1[(h*33 + 32)*DD + c] = o1; g_O2[(h*33 + 32)*DD + c] = o2;
    if (c == 0) {
        float oc1 = 0.f, oc2 = 0.f;
        for (int k = 0; k < 32; k++) {
            g_OC1[h*33 + k] = oc1; g_OC2[h*33 + k] = oc2;
            oc1 += g_TC1[h*32 + k]; oc2 += g_TC2[h*32 + k];
        }
        g_OC1[h*33 + 32] = oc1; g_OC2[h*33 + 32] = oc2;
    }
}

__global__ void k_global(const float* __restrict__ bias) {
    int i = blockIdx.x, tid = threadIdx.x;
    __shared__ int   s_r[4], s_kc[4];
    __shared__ float s_den[4], s_e1[4], s_e2[4];
    if (tid < 4) {
        int h = tid, id = (8 + h)*NN + i;
        float t = g_T[id], e1 = g_E1[id], e2 = g_E2[id];
        const float* key = g_sorted + h*NN;
        int lo = 0, hi = NN;
        while (lo < hi) { int mid = (lo + hi) >> 1; if (key[mid] <= t) lo = mid + 1; else hi = mid; }
        int r = lo;
        float c1 = 0.f, c2 = 0.f; int kc = 0;
        if (r) {
            int idx = r - 1; kc = idx >> 7;
            c1 = g_C1[h*NN + idx] + g_OC1[h*33 + kc];
            c2 = g_C2[h*NN + idx] + g_OC2[h*33 + kc];
        }
        float c1t = g_OC1[h*33 + 32];
        s_r[h] = r; s_kc[h] = kc; s_e1[h] = e1; s_e2[h] = e2;
        s_den[h] = e1 * (c1t - c1) + e2 * c2;
    }
    __syncthreads();
    int c = tid; float m = 0.f;
    #pragma unroll
    for (int h = 0; h < 4; h++) {
        int r = s_r[h];
        float p1 = 0.f, p2 = 0.f;
        if (r) {
            int idx = r - 1, kc = s_kc[h];
            p1 = g_P1[((long)h*NN + idx)*DD + c] + g_O1[(h*33 + kc)*DD + c];
            p2 = g_P2[((long)h*NN + idx)*DD + c] + g_O2[(h*33 + kc)*DD + c];
        }
        float t1 = g_O1[(h*33 + 32)*DD + c];
        float num = s_e1[h] * (t1 - p1) + s_e2[h] * p2;
        m += num / s_den[h];
    }
    m = 0.25f * m + bias[c];
    g_cath[(long)i*768 + 512 + c] = __float2half(fmaxf(m, 0.f));
}

// ---------------- MHA core (row range) ----------------
__global__ void k_attn(int rbase) {
    int n = rbase + blockIdx.x, tid = threadIdx.x;
    int h = tid >> 5, lane = tid & 31;
    const float* qp = g_q + (long)n*DD + h*DHH;
    float s[3];
    #pragma unroll
    for (int sc = 0; sc < 3; sc++) {
        const float* kp = g_k3 + ((long)sc*NN + n)*DD + h*DHH;
        float acc = qp[lane]*kp[lane] + qp[lane+32]*kp[lane+32];
        #pragma unroll
        for (int o = 16; o; o >>= 1) acc += __shfl_xor_sync(0xffffffffu, acc, o);
        s[sc] = acc * 0.125f;
    }
    float mx = fmaxf(s[0], fmaxf(s[1], s[2]));
    float e0 = expf(s[0]-mx), e1 = expf(s[1]-mx), e2 = expf(s[2]-mx);
    float inv = 1.f / (e0 + e1 + e2);
    e0 *= inv; e1 *= inv; e2 *= inv;
    #pragma unroll
    for (int p = 0; p < 2; p++) {
        int d0 = h*DHH + lane + p*32;
        long off = (long)n*DD + d0;
        float v = e0*g_v3[off] + e1*g_v3[(long)NN*DD + off] + e2*g_v3[2L*NN*DD + off];
        g_atth[off] = __float2half(v);
    }
}

// ---------------- LayerNorm + ReLU + residual (row range) ----------------
__global__ void k_final(const float* __restrict__ lng, const float* __restrict__ lnb,
                        float* __restrict__ out, int rbase) {
    int i = rbase + blockIdx.x, c = threadIdx.x;
    __shared__ float red[256];
    float v = g_hbuf[(long)i*DD + c];
    red[c] = v; __syncthreads();
    #pragma unroll
    for (int o = 128; o; o >>= 1) { if (c < o) red[c] += red[c+o]; __syncthreads(); }
    float mu = red[0] * (1.f / DD);
    __syncthreads();
    float dv = v - mu;
    red[c] = dv * dv; __syncthreads();
    #pragma unroll
    for (int o = 128; o; o >>= 1) { if (c < o) red[c] += red[c+o]; __syncthreads(); }
    float var = red[0] * (1.f / DD);
    float y = dv * rsqrtf(var + LNEPS) * lng[c] + lnb[c];
    y = fmaxf(y, 0.f);
    out[(long)i*DD + c] = y + g_xatt[(long)i*DD + c];
}

// ---------------- launch (multi-stream, tail pipelined in 2 row-halves) ----------------
extern "C" void kernel_launch(void* const* d_in, const int* in_sizes, int n_in,
                              void* d_out, int out_size) {
    const float* x    = (const float*)d_in[0];
    const int*   edges= (const int*)  d_in[1];
    const float* Wl   = (const float*)d_in[2];
    const float* als  = (const float*)d_in[3];
    const float* ald  = (const float*)d_in[4];
    const float* bl   = (const float*)d_in[5];
    const float* Wm   = (const float*)d_in[6];
    const float* ams  = (const float*)d_in[7];
    const float* amd  = (const float*)d_in[8];
    const float* bm   = (const float*)d_in[9];
    const float* Wg   = (const float*)d_in[10];
    const float* ags  = (const float*)d_in[11];
    const float* agd  = (const float*)d_in[12];
    const float* bg   = (const float*)d_in[13];
    const float* Wq   = (const float*)d_in[14];
    const float* bq   = (const float*)d_in[15];
    const float* Wk   = (const float*)d_in[16];
    const float* bk   = (const float*)d_in[17];
    const float* Wv   = (const float*)d_in[18];
    const float* bv   = (const float*)d_in[19];
    const float* Wo   = (const float*)d_in[20];
    const float* bo   = (const float*)d_in[21];
    const float* Wf   = (const float*)d_in[22];
    const float* bfv  = (const float*)d_in[23];
    const float* lng  = (const float*)d_in[24];
    const float* lnb  = (const float*)d_in[25];
    float* out = (float*)d_out;

    __half* zhp;    cudaGetSymbolAddress((void**)&zhp,   g_zh);
    __half* xhp;    cudaGetSymbolAddress((void**)&xhp,   g_xh);
    __half* whp;    cudaGetSymbolAddress((void**)&whp,   g_wh);
    __half* cathp;  cudaGetSymbolAddress((void**)&cathp, g_cath);
    float* qp;      cudaGetSymbolAddress((void**)&qp,    g_q);
    float* kp;      cudaGetSymbolAddress((void**)&kp,    g_k3);
    float* vp;      cudaGetSymbolAddress((void**)&vp,    g_v3);
    __half* atthp;  cudaGetSymbolAddress((void**)&atthp, g_atth);
    float* xattp;   cudaGetSymbolAddress((void**)&xattp, g_xatt);
    float* hp;      cudaGetSymbolAddress((void**)&hp,    g_hbuf);
    unsigned* mlp;  cudaGetSymbolAddress((void**)&mlp,   g_ML);

    static cudaStream_t s1, s2, s3;
    static cudaEvent_t eRoot, eConv, eSetup, eL, eG, eQ, eM1, eM2, eH1;
    static int inited = 0;
    if (!inited) {
        cudaStreamCreateWithFlags(&s1, cudaStreamNonBlocking);
        cudaStreamCreateWithFlags(&s2, cudaStreamNonBlocking);
        cudaStreamCreateWithFlags(&s3, cudaStreamNonBlocking);
        cudaEventCreateWithFlags(&eRoot,  cudaEventDisableTiming);
        cudaEventCreateWithFlags(&eConv,  cudaEventDisableTiming);
        cudaEventCreateWithFlags(&eSetup, cudaEventDisableTiming);
        cudaEventCreateWithFlags(&eL,     cudaEventDisableTiming);
        cudaEventCreateWithFlags(&eG,     cudaEventDisableTiming);
        cudaEventCreateWithFlags(&eQ,     cudaEventDisableTiming);
        cudaEventCreateWithFlags(&eM1,    cudaEventDisableTiming);
        cudaEventCreateWithFlags(&eM2,    cudaEventDisableTiming);
        cudaEventCreateWithFlags(&eH1,    cudaEventDisableTiming);
        inited = 1;
    }

    cudaEventRecord(eRoot, 0);

    // ---- s1: conv -> zM -> scoresM(+max) ----
    cudaStreamWaitEvent(s1, eRoot, 0);
    k_conv<<<(WTOT + 255)/256, 256, 0, s1>>>(x, Wl, Wm, Wg, Wq, Wk, Wv, Wo, Wf);
    cudaEventRecord(eConv, s1);
    k_hgemm2<<<dim3(2, 32, 4), 256, 0, s1>>>(xhp, DD, 0, whp + WOFF_M, DD, (long)DD*DD, 0,
                                      nullptr, (float*)0, 0, 0, zhp + (long)NN*1024, 1024, 256, DD);
    k_scores<<<(HH*NN)/8, 256, 0, s1>>>(1, ams, amd);

    // ---- s2: zL -> scoresL ----
    cudaStreamWaitEvent(s2, eConv, 0);
    k_hgemm2<<<dim3(2, 32, 4), 256, 0, s2>>>(xhp, DD, 0, whp + WOFF_L, DD, (long)DD*DD, 0,
                                      nullptr, (float*)0, 0, 0, zhp, 1024, 256, DD);
    k_scores<<<(HH*NN)/8, 256, 0, s2>>>(0, als, ald);

    // ---- s3: zG -> scoresG -> sort -> prefix -> global ----
    cudaStreamWaitEvent(s3, eConv, 0);
    k_hgemm2<<<dim3(2, 32, 4), 256, 0, s3>>>(xhp, DD, 0, whp + WOFF_G, DD, (long)DD*DD, 0,
                                      nullptr, (float*)0, 0, 0, zhp + 2L*NN*1024, 1024, 256, DD);
    k_scores<<<(HH*NN)/8, 256, 0, s3>>>(2, ags, agd);
    k_sort<<<HH, 1024, 0, s3>>>();
    k_prefA<<<HH*32, 256, 0, s3>>>();
    k_prefB<<<HH, 256, 0, s3>>>();
    k_global<<<NN, 256, 0, s3>>>(bg);
    cudaEventRecord(eG, s3);

    // ---- stream 0: graph mask setup ----
    k_detect<<<1, 32>>>((const unsigned*)edges);
    k_clear<<<(NN*NW + 255)/256, 256>>>();
    k_edges<<<(EE + 255)/256, 256>>>(edges);
    k_eye_ml<<<(NN + 255)/256, 256>>>();
    k_twohop<<<NN, NW>>>();
    k_transpose<<<2048, 256>>>();
    k_mm<<<NN, NW>>>();
    cudaEventRecord(eSetup, 0);

    // ---- stream 0: q projection ----
    cudaStreamWaitEvent(0, eConv, 0);
    k_hgemm2<<<dim3(2, 32, 1), 256>>>(xhp, DD, 0, whp + WOFF_Q, DD, 0, 0, bq,
                                      qp, DD, 0, (__half*)0, 0, 0, DD);
    cudaEventRecord(eQ, 0);

    // ---- s1: buildP -> pgemm half1 -> eM1 -> pgemm half2 -> eM2 ----
    cudaStreamWaitEvent(s1, eSetup, 0);
    k_buildP<<<dim3(256, 4), 256, 0, s1>>>();
    k_pgemm<<<dim3(2, 32, 8), 128, 0, s1>>>(0);
    cudaEventRecord(eM1, s1);
    k_pgemm<<<dim3(2, 32, 8), 128, 0, s1>>>(2048);
    cudaEventRecord(eM2, s1);

    // ---- s2: local gather (after scoresL) ----
    cudaStreamWaitEvent(s2, eSetup, 0);
    k_agg2<<<NN, 256, 0, s2>>>(0, mlp, bl, cathp + 0, 768);
    cudaEventRecord(eL, s2);

    // ---- s2: tail for rows 0..2047 (overlaps pgemm half2) ----
    cudaStreamWaitEvent(s2, eM1, 0);
    cudaStreamWaitEvent(s2, eG, 0);
    cudaStreamWaitEvent(s2, eQ, 0);
    k_midcomb<<<2048, 256, 0, s2>>>(bm, 0);
    k_hgemm2<<<dim3(2, 16, 1), 256, 0, s2>>>(cathp, 768, 0, whp + WOFF_F, 3*DD, 0, 0, bfv,
                                      hp, DD, 0, (__half*)0, 0, 0, 3*DD);
    k_hgemm2<<<dim3(2, 16, 3), 256, 0, s2>>>(cathp, 768, 256, whp + WOFF_K, DD, 0, 0, bk,
                                      kp, DD, (long)NN*DD, (__half*)0, 0, 0, DD);
    k_hgemm2<<<dim3(2, 16, 3), 256, 0, s2>>>(cathp, 768, 256, whp + WOFF_V, DD, 0, 0, bv,
                                      vp, DD, (long)NN*DD, (__half*)0, 0, 0, DD);
    k_attn<<<2048, 128, 0, s2>>>(0);
    k_hgemm2<<<dim3(2, 16, 1), 256, 0, s2>>>(atthp, DD, 0, whp + WOFF_O, DD, 0, 0, bo,
                                      xattp, DD, 0, (__half*)0, 0, 0, DD);
    k_final<<<2048, 256, 0, s2>>>(lng, lnb, out, 0);
    cudaEventRecord(eH1, s2);

    // ---- stream 0: tail for rows 2048..4095 ----
    cudaStreamWaitEvent(0, eM2, 0);
    cudaStreamWaitEvent(0, eL, 0);
    cudaStreamWaitEvent(0, eG, 0);
    k_midcomb<<<2048, 256>>>(bm, 2048);
    k_hgemm2<<<dim3(2, 16, 1), 256>>>(cathp + 2048L*768, 768, 0, whp + WOFF_F, 3*DD, 0, 0, bfv,
                                      hp + 2048L*DD, DD, 0, (__half*)0, 0, 0, 3*DD);
    k_hgemm2<<<dim3(2, 16, 3), 256>>>(cathp + 2048L*768, 768, 256, whp + WOFF_K, DD, 0, 0, bk,
                                      kp + 2048L*DD, DD, (long)NN*DD, (__half*)0, 0, 0, DD);
    k_hgemm2<<<dim3(2, 16, 3), 256>>>(cathp + 2048L*768, 768, 256, whp + WOFF_V, DD, 0, 0, bv,
                                      vp + 2048L*DD, DD, (long)NN*DD, (__half*)0, 0, 0, DD);
    k_attn<<<2048, 128>>>(2048);
    k_hgemm2<<<dim3(2, 16, 1), 256>>>(atthp + 2048L*DD, DD, 0, whp + WOFF_O, DD, 0, 0, bo,
                                      xattp + 2048L*DD, DD, 0, (__half*)0, 0, 0, DD);
    cudaStreamWaitEvent(0, eH1, 0);
    k_final<<<2048, 256>>>(lng, lnb, out, 2048);
}

// round 16
// speedup vs baseline: 1.0408x; 1.0408x over previous
#include <cuda_runtime.h>
#include <cuda_fp16.h>
#include <mma.h>
#include <math.h>
#include <stdint.h>

using namespace nvcuda;

#define NN 4096
#define DD 256
#define HH 4
#define DHH 64
#define EE 65536
#define NW 128
#define LNEPS 1e-5f

// ---------------- device scratch ----------------
__device__ int      g_is64;
__device__ unsigned g_A   [NN*NW];
__device__ unsigned g_ML  [NN*NW];
__device__ unsigned g_UND [NN*NW];
__device__ unsigned g_UNDT[NN*NW];
__device__ unsigned g_MM  [NN*NW];

__device__ __half g_zh  [3L*NN*HH*DD];
__device__ __half g_xh  [NN*DD];
__device__ __half g_wh  [3*HH*DD*DD + 4*DD*DD + DD*3*DD];
__device__ __half g_P   [4L*NN*NN];
__device__ float  g_den [HH*NN];
__device__ float  g_part [HH*NN*DD];
__device__ float  g_part2[HH*NN*DD];
__device__ unsigned g_maxu[HH];

__device__ float g_ssrc[3*HH*NN];
__device__ float g_F1  [3*HH*NN];
__device__ float g_F2  [3*HH*NN];
__device__ float g_T   [3*HH*NN];
__device__ float g_E1  [3*HH*NN];
__device__ float g_E2  [3*HH*NN];

__device__ __half g_cath[NN*3*DD];
__device__ float g_sorted[HH*NN];
__device__ int   g_perm  [HH*NN];
__device__ float g_P1[HH*NN*DD];
__device__ float g_P2[HH*NN*DD];
__device__ float g_C1[HH*NN];
__device__ float g_C2[HH*NN];
__device__ float g_T1[HH*32*DD], g_T2[HH*32*DD];
__device__ float g_O1[HH*33*DD], g_O2[HH*33*DD];
__device__ float g_TC1[HH*32], g_TC2[HH*32];
__device__ float g_OC1[HH*33], g_OC2[HH*33];

__device__ float  g_q   [NN*DD];
__device__ float  g_k3  [3*NN*DD];
__device__ float  g_v3  [3*NN*DD];
__device__ __half g_atth[NN*DD];
__device__ float  g_xatt[NN*DD];
__device__ float  g_hbuf[NN*DD];

#define WOFF_L  0
#define WOFF_M  262144
#define WOFF_G  524288
#define WOFF_Q  786432
#define WOFF_K  851968
#define WOFF_V  917504
#define WOFF_O  983040
#define WOFF_F  1048576
#define WTOT    1245184

__device__ __forceinline__ unsigned fkey(float f) {
    unsigned u = __float_as_uint(f);
    return (u >> 31) ? ~u : (u | 0x80000000u);
}
__device__ __forceinline__ float fdec(unsigned k) {
    unsigned u = (k >> 31) ? (k & 0x7fffffffu) : ~k;
    return __uint_as_float(u);
}

__device__ __forceinline__ void cp16(uint32_t dst, const void* src) {
    asm volatile("cp.async.cg.shared.global [%0], [%1], 16;" :: "r"(dst), "l"(src));
}
#define CP_COMMIT() asm volatile("cp.async.commit_group;" ::: "memory")
#define CP_WAIT0()  asm volatile("cp.async.wait_group 0;" ::: "memory")

// ---------------- setup kernels ----------------
__global__ void k_detect(const unsigned* e) {
    if (threadIdx.x == 0) {
        int all0 = 1;
        for (int i = 0; i < 128; i++) if (e[2*i+1] != 0u) { all0 = 0; break; }
        g_is64 = all0;
    }
}

__global__ void k_clear() {
    int i = blockIdx.x * blockDim.x + threadIdx.x;
    if (i < NN*NW) { g_A[i] = 0u; g_ML[i] = 0u; }
}

__global__ void k_edges(const int* e) {
    int i = blockIdx.x * blockDim.x + threadIdx.x;
    if (i >= EE) return;
    int s, t;
    if (g_is64) { s = e[2*i]; t = e[2*(EE+i)]; }
    else        { s = e[i];   t = e[EE+i];     }
    atomicOr(&g_A [s*NW + (t>>5)], 1u << (t & 31));
    atomicOr(&g_ML[t*NW + (s>>5)], 1u << (s & 31));
}

__global__ void k_eye_ml() {
    int i = blockIdx.x * blockDim.x + threadIdx.x;
    if (i < NN) g_ML[i*NW + (i>>5)] |= 1u << (i & 31);
}

__global__ void k_twohop() {
    int i = blockIdx.x, w = threadIdx.x;
    __shared__ unsigned sh[NW];
    sh[w] = g_A[i*NW + w];
    __syncthreads();
    unsigned acc = sh[w];
    for (int w2 = 0; w2 < NW; w2++) {
        unsigned bits = sh[w2];
        while (bits) {
            int b = __ffs(bits) - 1; bits &= bits - 1;
            acc |= g_A[((w2<<5)+b)*NW + w];
        }
    }
    g_UND[i*NW + w] = acc;
}

__global__ void k_transpose() {
    int tile = blockIdx.x * 8 + (threadIdx.x >> 5);
    int lane = threadIdx.x & 31;
    int ti = tile >> 7, tj = tile & 127;
    __shared__ unsigned sm[8][32];
    int wslot = threadIdx.x >> 5;
    sm[wslot][lane] = g_UND[(ti*32 + lane)*NW + tj];
    __syncwarp();
    unsigned y = 0;
    #pragma unroll
    for (int b = 0; b < 32; b++) y |= ((sm[wslot][b] >> lane) & 1u) << b;
    g_UNDT[(tj*32 + lane)*NW + ti] = y;
}

__global__ void k_mm() {
    int i = blockIdx.x, w = threadIdx.x;
    unsigned res = g_UND[i*NW + w] | g_UNDT[i*NW + w];
    if (w == (i >> 5)) res |= 1u << (i & 31);
    g_MM[i*NW + w] = res;
}

__global__ void k_conv(const float* __restrict__ x,
                       const float* Wl, const float* Wm, const float* Wg,
                       const float* Wq, const float* Wk, const float* Wv,
                       const float* Wo, const float* Wf) {
    int i = blockIdx.x * blockDim.x + threadIdx.x;
    if (i < 4) g_maxu[i] = 0u;
    if (i < NN*DD) g_xh[i] = __float2half(x[i]);
    if (i < WTOT) {
        float v;
        if      (i < WOFF_M) v = Wl[i - WOFF_L];
        else if (i < WOFF_G) v = Wm[i - WOFF_M];
        else if (i < WOFF_Q) v = Wg[i - WOFF_G];
        else if (i < WOFF_K) v = Wq[i - WOFF_Q];
        else if (i < WOFF_V) v = Wk[i - WOFF_K];
        else if (i < WOFF_O) v = Wv[i - WOFF_V];
        else if (i < WOFF_F) v = Wo[i - WOFF_O];
        else                 v = Wf[i - WOFF_F];
        g_wh[i] = __float2half(v);
    }
}

// ---------------- 128x128 double-buffered wmma GEMM (projections) ----------------
__global__ __launch_bounds__(256, 2)
void k_hgemm2(const __half* __restrict__ A, int lda, long sA,
              const __half* __restrict__ B, int ldb, long sB, int brm,
              const float* __restrict__ bias,
              float* __restrict__ Cf, int ldc, long sC,
              __half* Ch, int ldch, long sCh, int K) {
    int bz = blockIdx.z;
    const __half* Ae = A + (long)bz * sA;
    const __half* Be = B + (long)bz * sB;
    float* cf = Cf ? Cf + (long)bz * sC : (float*)0;
    __half* ch = Ch ? Ch + (long)bz * sCh : (__half*)0;
    int bm = blockIdx.y << 7;
    int bn = blockIdx.x << 7;
    int tid = threadIdx.x;
    int wid = tid >> 5, lane = tid & 31;
    int wm = wid >> 2, wn = wid & 3;

    __shared__ __half As[2][5120];
    __shared__ __half Bs[2][5120];

    wmma::fragment<wmma::accumulator,16,16,16,float> acc[4][2];
    #pragma unroll
    for (int i = 0; i < 4; i++)
        #pragma unroll
        for (int j = 0; j < 2; j++) wmma::fill_fragment(acc[i][j], 0.f);

    int KT = K >> 5;
    int i0 = tid*2, i1 = tid*2 + 1;

    {
        int r0 = i0>>2, s0 = i0&3, r1 = i1>>2, s1 = i1&3;
        *(uint4*)&As[0][r0*40 + s0*8] = *(const uint4*)&Ae[(long)(bm+r0)*lda + s0*8];
        *(uint4*)&As[0][r1*40 + s1*8] = *(const uint4*)&Ae[(long)(bm+r1)*lda + s1*8];
        if (brm) {
            int br0 = i0>>4, bs0 = i0&15, br1 = i1>>4, bs1 = i1&15;
            *(uint4*)&Bs[0][br0*144 + bs0*8] = *(const uint4*)&Be[(long)br0*ldb + bn + bs0*8];
            *(uint4*)&Bs[0][br1*144 + bs1*8] = *(const uint4*)&Be[(long)br1*ldb + bn + bs1*8];
        } else {
            *(uint4*)&Bs[0][r0*40 + s0*8] = *(const uint4*)&Be[(long)(bn+r0)*ldb + s0*8];
            *(uint4*)&Bs[0][r1*40 + s1*8] = *(const uint4*)&Be[(long)(bn+r1)*ldb + s1*8];
        }
    }
    __syncthreads();

    int buf = 0;
    for (int kt = 0; kt < KT; kt++) {
        uint4 pa0, pa1, pb0, pb1;
        int havenext = (kt + 1 < KT);
        int k0n = (kt + 1) << 5;
        int r0 = i0>>2, s0 = i0&3, r1 = i1>>2, s1 = i1&3;
        int br0 = i0>>4, bs0 = i0&15, br1 = i1>>4, bs1 = i1&15;
        if (havenext) {
            pa0 = *(const uint4*)&Ae[(long)(bm+r0)*lda + k0n + s0*8];
            pa1 = *(const uint4*)&Ae[(long)(bm+r1)*lda + k0n + s1*8];
            if (brm) {
                pb0 = *(const uint4*)&Be[(long)(k0n+br0)*ldb + bn + bs0*8];
                pb1 = *(const uint4*)&Be[(long)(k0n+br1)*ldb + bn + bs1*8];
            } else {
                pb0 = *(const uint4*)&Be[(long)(bn+r0)*ldb + k0n + s0*8];
                pb1 = *(const uint4*)&Be[(long)(bn+r1)*ldb + k0n + s1*8];
            }
        }
        #pragma unroll
        for (int kk = 0; kk < 2; kk++) {
            wmma::fragment<wmma::matrix_a,16,16,16,__half,wmma::row_major> af[4];
            #pragma unroll
            for (int i = 0; i < 4; i++)
                wmma::load_matrix_sync(af[i], &As[buf][(wm*64 + i*16)*40 + kk*16], 40);
            if (brm) {
                wmma::fragment<wmma::matrix_b,16,16,16,__half,wmma::row_major> bf[2];
                #pragma unroll
                for (int j = 0; j < 2; j++)
                    wmma::load_matrix_sync(bf[j], &Bs[buf][kk*16*144 + wn*32 + j*16], 144);
                #pragma unroll
                for (int i = 0; i < 4; i++)
                    #pragma unroll
                    for (int j = 0; j < 2; j++)
                        wmma::mma_sync(acc[i][j], af[i], bf[j], acc[i][j]);
            } else {
                wmma::fragment<wmma::matrix_b,16,16,16,__half,wmma::col_major> bf[2];
                #pragma unroll
                for (int j = 0; j < 2; j++)
                    wmma::load_matrix_sync(bf[j], &Bs[buf][(wn*32 + j*16)*40 + kk*16], 40);
                #pragma unroll
                for (int i = 0; i < 4; i++)
                    #pragma unroll
                    for (int j = 0; j < 2; j++)
                        wmma::mma_sync(acc[i][j], af[i], bf[j], acc[i][j]);
            }
        }
        if (havenext) {
            *(uint4*)&As[buf^1][r0*40 + s0*8] = pa0;
            *(uint4*)&As[buf^1][r1*40 + s1*8] = pa1;
            if (brm) {
                *(uint4*)&Bs[buf^1][br0*144 + bs0*8] = pb0;
                *(uint4*)&Bs[buf^1][br1*144 + bs1*8] = pb1;
            } else {
                *(uint4*)&Bs[buf^1][r0*40 + s0*8] = pb0;
                *(uint4*)&Bs[buf^1][r1*40 + s1*8] = pb1;
            }
        }
        __syncthreads();
        buf ^= 1;
    }

    float* scratch = (float*)&As[0][0] + wid * 320;
    int er = lane >> 1, ec = (lane & 1) * 8;
    #pragma unroll
    for (int i = 0; i < 4; i++) {
        #pragma unroll
        for (int j = 0; j < 2; j++) {
            wmma::store_matrix_sync(scratch, acc[i][j], 20, wmma::mem_row_major);
            __syncwarp();
            int m = bm + wm*64 + i*16 + er;
            int n = bn + wn*32 + j*16 + ec;
            float4 v0 = *(float4*)&scratch[er*20 + ec];
            float4 v1 = *(float4*)&scratch[er*20 + ec + 4];
            if (bias) {
                v0.x += bias[n];   v0.y += bias[n+1]; v0.z += bias[n+2]; v0.w += bias[n+3];
                v1.x += bias[n+4]; v1.y += bias[n+5]; v1.z += bias[n+6]; v1.w += bias[n+7];
            }
            if (cf) {
                *(float4*)&cf[(long)m*ldc + n]     = v0;
                *(float4*)&cf[(long)m*ldc + n + 4] = v1;
            }
            if (ch) {
                __half2 h0 = __floats2half2_rn(v0.x, v0.y);
                __half2 h1 = __floats2half2_rn(v0.z, v0.w);
                __half2 h2 = __floats2half2_rn(v1.x, v1.y);
                __half2 h3 = __floats2half2_rn(v1.z, v1.w);
                uint4 pk;
                pk.x = *(unsigned*)&h0; pk.y = *(unsigned*)&h1;
                pk.z = *(unsigned*)&h2; pk.w = *(unsigned*)&h3;
                *(uint4*)&ch[(long)m*ldch + n] = pk;
            }
            __syncwarp();
        }
    }
}

// ---------------- P@z GEMM: R12 body + row-half offset ----------------
// grid (2, 32, 8): bn (128 cols), bm (64 rows in half), bz = head*2 + ks.
__global__ __launch_bounds__(128)
void k_pgemm(int rbase) {
    int bz = blockIdx.z;
    int h  = bz >> 1;
    int ks = bz & 1;
    int koff = ks << 11;
    const __half* Ae = g_P + (long)h*NN*NN;
    const __half* Be = g_zh + (long)NN*1024 + h*256;
    float* cf = (ks ? g_part2 : g_part) + (long)h*NN*DD;
    int bm = rbase + (blockIdx.y << 6);
    int bn = blockIdx.x << 7;
    int tid = threadIdx.x;
    int wid = tid >> 5, lane = tid & 31;

    __shared__ __half As[2][64*40];
    __shared__ __half Bs[2][32*136];

    wmma::fragment<wmma::accumulator,16,16,16,float> acc[4][2];
    #pragma unroll
    for (int i = 0; i < 4; i++)
        #pragma unroll
        for (int j = 0; j < 2; j++) wmma::fill_fragment(acc[i][j], 0.f);

    int ua0 = tid*2, ua1 = tid*2 + 1;
    int ar0 = ua0 >> 2, as0 = ua0 & 3, ar1 = ua1 >> 2, as1 = ua1 & 3;

    {
        int k0 = koff;
        cp16((uint32_t)__cvta_generic_to_shared(&As[0][ar0*40 + as0*8]),
             &Ae[(long)(bm+ar0)*NN + k0 + as0*8]);
        cp16((uint32_t)__cvta_generic_to_shared(&As[0][ar1*40 + as1*8]),
             &Ae[(long)(bm+ar1)*NN + k0 + as1*8]);
        #pragma unroll
        for (int t = 0; t < 4; t++) {
            int u = tid*4 + t;
            int br = u >> 4, bs = u & 15;
            cp16((uint32_t)__cvta_generic_to_shared(&Bs[0][br*136 + bs*8]),
                 &Be[(long)(k0+br)*1024 + bn + bs*8]);
        }
        CP_COMMIT();
        CP_WAIT0();
    }
    __syncthreads();

    int buf = 0;
    for (int kt = 0; kt < 64; kt++) {
        if (kt + 1 < 64) {
            int k0 = koff + ((kt + 1) << 5);
            cp16((uint32_t)__cvta_generic_to_shared(&As[buf^1][ar0*40 + as0*8]),
                 &Ae[(long)(bm+ar0)*NN + k0 + as0*8]);
            cp16((uint32_t)__cvta_generic_to_shared(&As[buf^1][ar1*40 + as1*8]),
                 &Ae[(long)(bm+ar1)*NN + k0 + as1*8]);
            #pragma unroll
            for (int t = 0; t < 4; t++) {
                int u = tid*4 + t;
                int br = u >> 4, bs = u & 15;
                cp16((uint32_t)__cvta_generic_to_shared(&Bs[buf^1][br*136 + bs*8]),
                     &Be[(long)(k0+br)*1024 + bn + bs*8]);
            }
            CP_COMMIT();
        }
        #pragma unroll
        for (int kk = 0; kk < 2; kk++) {
            wmma::fragment<wmma::matrix_a,16,16,16,__half,wmma::row_major> af[4];
            #pragma unroll
            for (int i = 0; i < 4; i++)
                wmma::load_matrix_sync(af[i], &As[buf][(i*16)*40 + kk*16], 40);
            wmma::fragment<wmma::matrix_b,16,16,16,__half,wmma::row_major> bf[2];
            #pragma unroll
            for (int j = 0; j < 2; j++)
                wmma::load_matrix_sync(bf[j], &Bs[buf][kk*16*136 + wid*32 + j*16], 136);
            #pragma unroll
            for (int i = 0; i < 4; i++)
                #pragma unroll
                for (int j = 0; j < 2; j++)
                    wmma::mma_sync(acc[i][j], af[i], bf[j], acc[i][j]);
        }
        CP_WAIT0();
        __syncthreads();
        buf ^= 1;
    }

    float* scratch = (float*)&As[0][0] + wid * 320;
    int er = lane >> 1, ec = (lane & 1) * 8;
    #pragma unroll
    for (int i = 0; i < 4; i++) {
        #pragma unroll
        for (int j = 0; j < 2; j++) {
            wmma::store_matrix_sync(scratch, acc[i][j], 20, wmma::mem_row_major);
            __syncwarp();
            int m = bm + i*16 + er;
            int n = bn + wid*32 + j*16 + ec;
            *(float4*)&cf[(long)m*DD + n]     = *(float4*)&scratch[er*20 + ec];
            *(float4*)&cf[(long)m*DD + n + 4] = *(float4*)&scratch[er*20 + ec + 4];
            __syncwarp();
        }
    }
}

// ---------------- attention scalars, per scale ----------------
__global__ void k_scores(int sc, const float* __restrict__ as, const float* __restrict__ ad) {
    int item = blockIdx.x * 8 + (threadIdx.x >> 5);
    int lane = threadIdx.x & 31;
    if (item >= HH*NN) return;
    int n = item & (NN - 1);
    int h = item >> 12;
    int gi = sc*HH*NN + item;
    const __half* zr = g_zh + ((long)sc*NN + n)*1024 + h*DD;
    float s1 = 0.f, s2 = 0.f;
    for (int d0 = lane; d0 < DD; d0 += 32) {
        float zv = __half2float(zr[d0]);
        s1 += zv * as[h*DD + d0];
        s2 += zv * ad[h*DD + d0];
    }
    #pragma unroll
    for (int o = 16; o; o >>= 1) {
        s1 += __shfl_down_sync(0xffffffffu, s1, o);
        s2 += __shfl_down_sync(0xffffffffu, s2, o);
    }
    if (lane == 0) {
        g_ssrc[gi] = s1; g_F1[gi] = expf(s1);  g_F2[gi] = expf(0.2f * s1);
        g_T[gi] = -s2;   g_E1[gi] = expf(s2);  g_E2[gi] = expf(0.2f * s2);
        if (sc == 1) atomicMax(&g_maxu[h], fkey(s1));
    }
}

// ---------------- LOCAL sparse gather ----------------
__global__ void k_agg2(int sc, const unsigned* __restrict__ M,
                       const float* __restrict__ bias,
                       __half* __restrict__ out, int ldo) {
    int i = blockIdx.x, tid = threadIdx.x;
    __shared__ int   s_idx[NN];
    __shared__ float s_w[64][4];
    __shared__ int   s_cntw[NW], s_off[NW + 1];
    __shared__ float s_t[4], s_e1[4], s_e2[4];
    __shared__ float s_acc[2][4][32][8];
    __shared__ float s_den[2][4];
    if (tid < 4) {
        int id = (sc*4 + tid) * NN + i;
        s_t[tid] = g_T[id]; s_e1[tid] = g_E1[id]; s_e2[tid] = g_E2[id];
    }
    if (tid < NW) s_cntw[tid] = __popc(M[i*NW + tid]);
    __syncthreads();
    if (tid == 0) {
        int a = 0;
        for (int w = 0; w < NW; w++) { s_off[w] = a; a += s_cntw[w]; }
        s_off[NW] = a;
    }
    __syncthreads();
    if (tid < NW) {
        unsigned bits = M[i*NW + tid];
        int p = s_off[tid];
        while (bits) { int b = __ffs(bits) - 1; bits &= bits - 1; s_idx[p++] = (tid<<5) + b; }
    }
    __syncthreads();
    int deg = s_off[NW];
    int grp = tid >> 7;
    int t2  = tid & 127;
    int h   = t2 >> 5;
    int slot = t2 & 31;
    const uint4* zh = (const uint4*)(g_zh + (long)sc*NN*1024);
    float acc[8] = {0,0,0,0,0,0,0,0};
    float den = 0.f;
    int jw = tid & 63, hw = tid >> 6;
    for (int base = 0; base < deg; base += 64) {
        int cnt = min(64, deg - base);
        if (jw < cnt) {
            int j = s_idx[base + jw];
            int id = (sc*4 + hw) * NN + j;
            float sj = g_ssrc[id];
            s_w[jw][hw] = (sj > s_t[hw]) ? s_e1[hw] * g_F1[id] : s_e2[hw] * g_F2[id];
        }
        __syncthreads();
        for (int q = grp; q < cnt; q += 2) {
            int j = s_idx[base + q];
            uint4 zv = zh[(long)j * 128 + h*32 + slot];
            float w = s_w[q][h];
            den += w;
            __half2 p0 = *(__half2*)&zv.x, p1 = *(__half2*)&zv.y;
            __half2 p2 = *(__half2*)&zv.z, p3 = *(__half2*)&zv.w;
            float2 f0 = __half22float2(p0), f1 = __half22float2(p1);
            float2 f2 = __half22float2(p2), f3 = __half22float2(p3);
            acc[0] += w*f0.x; acc[1] += w*f0.y;
            acc[2] += w*f1.x; acc[3] += w*f1.y;
            acc[4] += w*f2.x; acc[5] += w*f2.y;
            acc[6] += w*f3.x; acc[7] += w*f3.y;
        }
        __syncthreads();
    }
    #pragma unroll
    for (int k = 0; k < 8; k++) s_acc[grp][h][slot][k] = acc[k];
    if (slot == 0) s_den[grp][h] = den;
    __syncthreads();
    int c = tid;
    float m = 0.f;
    #pragma unroll
    for (int hh2 = 0; hh2 < 4; hh2++) {
        float d = s_den[0][hh2] + s_den[1][hh2];
        float v = s_acc[0][hh2][c>>3][c&7] + s_acc[1][hh2][c>>3][c&7];
        m += v / d;
    }
    out[(long)i * ldo + c] = __float2half(fmaxf(0.25f * m + bias[c], 0.f));
}

// ---------------- MID: dense P build (row-half) + combine ----------------
__global__ void k_buildP(int rbase) {
    int grp = blockIdx.x, h = blockIdx.y;
    int tid = threadIdx.x;
    int row0 = rbase + grp * 16;
    int base = (4 + h) * NN;
    __shared__ float sf1[256], sf2[256], ssj[256];
    __shared__ unsigned smask[16][8];
    __shared__ float ra[16], rb[16], rt[16];
    __shared__ float sred[256];
    if (tid < 16) {
        int i = row0 + tid;
        float t = g_T[base + i];
        float sdst = -t;
        float m = sdst + fdec(g_maxu[h]);
        m = m > 0.f ? m : 0.2f * m;
        ra[tid] = expf(sdst - m);
        rb[tid] = expf(0.2f * sdst - m);
        rt[tid] = t;
    }
    float dsum[16];
    #pragma unroll
    for (int r = 0; r < 16; r++) dsum[r] = 0.f;
    __syncthreads();
    for (int c0 = 0; c0 < NN; c0 += 256) {
        sf1[tid] = g_F1[base + c0 + tid];
        sf2[tid] = g_F2[base + c0 + tid];
        ssj[tid] = g_ssrc[base + c0 + tid];
        if (tid < 128) smask[tid>>3][tid&7] = g_MM[(row0 + (tid>>3))*NW + (c0>>5) + (tid&7)];
        __syncthreads();
        float f1 = sf1[tid], f2 = sf2[tid], sj = ssj[tid];
        int wd = tid >> 5; unsigned bm = 1u << (tid & 31);
        long pbase = ((long)h*NN + row0)*NN + c0 + tid;
        #pragma unroll
        for (int r = 0; r < 16; r++) {
            float w = 0.f;
            if (smask[r][wd] & bm)
                w = (sj > rt[r]) ? ra[r]*f1 : rb[r]*f2;
            dsum[r] += w;
            g_P[pbase + (long)r*NN] = __float2half(w);
        }
        __syncthreads();
    }
    for (int r = 0; r < 16; r++) {
        sred[tid] = dsum[r]; __syncthreads();
        for (int o = 128; o; o >>= 1) { if (tid < o) sred[tid] += sred[tid+o]; __syncthreads(); }
        if (tid == 0) g_den[h*NN + row0 + r] = sred[0];
        __syncthreads();
    }
}

__global__ void k_midcomb(const float* __restrict__ bias) {
    int i = blockIdx.x, c = threadIdx.x;
    float m = 0.f;
    #pragma unroll
    for (int h = 0; h < 4; h++) {
        long idx = ((long)h*NN + i)*DD + c;
        m += (g_part[idx] + g_part2[idx]) / g_den[h*NN + i];
    }
    g_cath[(long)i*768 + 256 + c] = __float2half(fmaxf(0.25f * m + bias[c], 0.f));
}

// ---------------- global scale ----------------
__global__ void k_sort() {
    int h = blockIdx.x, tid = threadIdx.x;
    __shared__ float key[NN];
    __shared__ int   idx[NN];
    for (int i = tid; i < NN; i += 1024) { key[i] = g_ssrc[(8 + h)*NN + i]; idx[i] = i; }
    __syncthreads();
    for (int k = 2; k <= NN; k <<= 1) {
        for (int j = k >> 1; j > 0; j >>= 1) {
            for (int i = tid; i < NN; i += 1024) {
                int ixj = i ^ j;
                if (ixj > i) {
                    bool up = (i & k) == 0;
                    float a = key[i], b = key[ixj];
                    if ((a > b) == up) {
                        key[i] = b; key[ixj] = a;
                        int t = idx[i]; idx[i] = idx[ixj]; idx[ixj] = t;
                    }
                }
            }
            __syncthreads();
        }
    }
    for (int i = tid; i < NN; i += 1024) { g_sorted[h*NN + i] = key[i]; g_perm[h*NN + i] = idx[i]; }
}

__global__ void k_prefA() {
    int h = blockIdx.x >> 5, k = blockIdx.x & 31;
    int c = threadIdx.x;
    int base = (8 + h) * NN;
    float a1 = 0.f, a2 = 0.f, c1 = 0.f, c2 = 0.f;
    int r0 = k << 7;
    for (int l = 0; l < 128; l++) {
        int r = r0 + l;
        int j = g_perm[h*NN + r];
        float f1 = g_F1[base + j], f2 = g_F2[base + j];
        float zv = __half2float(g_zh[((long)2*NN + j)*1024 + h*DD + c]);
        a1 += f1 * zv; a2 += f2 * zv;
        g_P1[((long)h*NN + r)*DD + c] = a1;
        g_P2[((long)h*NN + r)*DD + c] = a2;
        if (c == 0) { c1 += f1; c2 += f2; g_C1[h*NN + r] = c1; g_C2[h*NN + r] = c2; }
    }
    g_T1[(h*32 + k)*DD + c] = a1;
    g_T2[(h*32 + k)*DD + c] = a2;
    if (c == 0) { g_TC1[h*32 + k] = c1; g_TC2[h*32 + k] = c2; }
}

__global__ void k_prefB() {
    int h = blockIdx.x, c = threadIdx.x;
    float o1 = 0.f, o2 = 0.f;
    for (int k = 0; k < 32; k++) {
        g_O1[(h*33 + k)*DD + c] = o1; g_O2[(h*33 + k)*DD + c] = o2;
        o1 += g_T1[(h*32 + k)*DD + c]; o2 += g_T2[(h*32 + k)*DD + c];
    }
    g_O1[(h*33 + 32)*DD + c] = o1; g_O2[(h*33 + 32)*DD + c] = o2;
    if (c == 0) {
        float oc1 = 0.f, oc2 = 0.f;
        for (int k = 0; k < 32; k++) {
            g_OC1[h*33 + k] = oc1; g_OC2[h*33 + k] = oc2;
            oc1 += g_TC1[h*32 + k]; oc2 += g_TC2[h*32 + k];
        }
        g_OC1[h*33 + 32] = oc1; g_OC2[h*33 + 32] = oc2;
    }
}

__global__ void k_global(const float* __restrict__ bias) {
    int i = blockIdx.x, tid = threadIdx.x;
    __shared__ int   s_r[4], s_kc[4];
    __shared__ float s_den[4], s_e1[4], s_e2[4];
    if (tid < 4) {
        int h = tid, id = (8 + h)*NN + i;
        float t = g_T[id], e1 = g_E1[id], e2 = g_E2[id];
        const float* key = g_sorted + h*NN;
        int lo = 0, hi = NN;
        while (lo < hi) { int mid = (lo + hi) >> 1; if (key[mid] <= t) lo = mid + 1; else hi = mid; }
        int r = lo;
        float c1 = 0.f, c2 = 0.f; int kc = 0;
        if (r) {
            int idx = r - 1; kc = idx >> 7;
            c1 = g_C1[h*NN + idx] + g_OC1[h*33 + kc];
            c2 = g_C2[h*NN + idx] + g_OC2[h*33 + kc];
        }
        float c1t = g_OC1[h*33 + 32];
        s_r[h] = r; s_kc[h] = kc; s_e1[h] = e1; s_e2[h] = e2;
        s_den[h] = e1 * (c1t - c1) + e2 * c2;
    }
    __syncthreads();
    int c = tid; float m = 0.f;
    #pragma unroll
    for (int h = 0; h < 4; h++) {
        int r = s_r[h];
        float p1 = 0.f, p2 = 0.f;
        if (r) {
            int idx = r - 1, kc = s_kc[h];
            p1 = g_P1[((long)h*NN + idx)*DD + c] + g_O1[(h*33 + kc)*DD + c];
            p2 = g_P2[((long)h*NN + idx)*DD + c] + g_O2[(h*33 + kc)*DD + c];
        }
        float t1 = g_O1[(h*33 + 32)*DD + c];
        float num = s_e1[h] * (t1 - p1) + s_e2[h] * p2;
        m += num / s_den[h];
    }
    m = 0.25f * m + bias[c];
    g_cath[(long)i*768 + 512 + c] = __float2half(fmaxf(m, 0.f));
}

// ---------------- MHA core ----------------
__global__ void k_attn() {
    int n = blockIdx.x, tid = threadIdx.x;
    int h = tid >> 5, lane = tid & 31;
    const float* qp = g_q + (long)n*DD + h*DHH;
    float s[3];
    #pragma unroll
    for (int sc = 0; sc < 3; sc++) {
        const float* kp = g_k3 + ((long)sc*NN + n)*DD + h*DHH;
        float acc = qp[lane]*kp[lane] + qp[lane+32]*kp[lane+32];
        #pragma unroll
        for (int o = 16; o; o >>= 1) acc += __shfl_xor_sync(0xffffffffu, acc, o);
        s[sc] = acc * 0.125f;
    }
    float mx = fmaxf(s[0], fmaxf(s[1], s[2]));
    float e0 = expf(s[0]-mx), e1 = expf(s[1]-mx), e2 = expf(s[2]-mx);
    float inv = 1.f / (e0 + e1 + e2);
    e0 *= inv; e1 *= inv; e2 *= inv;
    #pragma unroll
    for (int p = 0; p < 2; p++) {
        int d0 = h*DHH + lane + p*32;
        long off = (long)n*DD + d0;
        float v = e0*g_v3[off] + e1*g_v3[(long)NN*DD + off] + e2*g_v3[2L*NN*DD + off];
        g_atth[off] = __float2half(v);
    }
}

// ---------------- LayerNorm + ReLU + residual ----------------
__global__ void k_final(const float* __restrict__ lng, const float* __restrict__ lnb,
                        float* __restrict__ out) {
    int i = blockIdx.x, c = threadIdx.x;
    __shared__ float red[256];
    float v = g_hbuf[(long)i*DD + c];
    red[c] = v; __syncthreads();
    #pragma unroll
    for (int o = 128; o; o >>= 1) { if (c < o) red[c] += red[c+o]; __syncthreads(); }
    float mu = red[0] * (1.f / DD);
    __syncthreads();
    float dv = v - mu;
    red[c] = dv * dv; __syncthreads();
    #pragma unroll
    for (int o = 128; o; o >>= 1) { if (c < o) red[c] += red[c+o]; __syncthreads(); }
    float var = red[0] * (1.f / DD);
    float y = dv * rsqrtf(var + LNEPS) * lng[c] + lnb[c];
    y = fmaxf(y, 0.f);
    out[(long)i*DD + c] = y + g_xatt[(long)i*DD + c];
}

// ---------------- launch (R12 schedule + buildP/pgemm producer-consumer pipeline) ----------------
extern "C" void kernel_launch(void* const* d_in, const int* in_sizes, int n_in,
                              void* d_out, int out_size) {
    const float* x    = (const float*)d_in[0];
    const int*   edges= (const int*)  d_in[1];
    const float* Wl   = (const float*)d_in[2];
    const float* als  = (const float*)d_in[3];
    const float* ald  = (const float*)d_in[4];
    const float* bl   = (const float*)d_in[5];
    const float* Wm   = (const float*)d_in[6];
    const float* ams  = (const float*)d_in[7];
    const float* amd  = (const float*)d_in[8];
    const float* bm   = (const float*)d_in[9];
    const float* Wg   = (const float*)d_in[10];
    const float* ags  = (const float*)d_in[11];
    const float* agd  = (const float*)d_in[12];
    const float* bg   = (const float*)d_in[13];
    const float* Wq   = (const float*)d_in[14];
    const float* bq   = (const float*)d_in[15];
    const float* Wk   = (const float*)d_in[16];
    const float* bk   = (const float*)d_in[17];
    const float* Wv   = (const float*)d_in[18];
    const float* bv   = (const float*)d_in[19];
    const float* Wo   = (const float*)d_in[20];
    const float* bo   = (const float*)d_in[21];
    const float* Wf   = (const float*)d_in[22];
    const float* bfv  = (const float*)d_in[23];
    const float* lng  = (const float*)d_in[24];
    const float* lnb  = (const float*)d_in[25];
    float* out = (float*)d_out;

    __half* zhp;    cudaGetSymbolAddress((void**)&zhp,   g_zh);
    __half* xhp;    cudaGetSymbolAddress((void**)&xhp,   g_xh);
    __half* whp;    cudaGetSymbolAddress((void**)&whp,   g_wh);
    __half* cathp;  cudaGetSymbolAddress((void**)&cathp, g_cath);
    float* qp;      cudaGetSymbolAddress((void**)&qp,    g_q);
    float* kp;      cudaGetSymbolAddress((void**)&kp,    g_k3);
    float* vp;      cudaGetSymbolAddress((void**)&vp,    g_v3);
    __half* atthp;  cudaGetSymbolAddress((void**)&atthp, g_atth);
    float* xattp;   cudaGetSymbolAddress((void**)&xattp, g_xatt);
    float* hp;      cudaGetSymbolAddress((void**)&hp,    g_hbuf);
    unsigned* mlp;  cudaGetSymbolAddress((void**)&mlp,   g_ML);

    static cudaStream_t s1, s2, s3;
    static cudaEvent_t eRoot, eConv, eSetup, eL, eG, eB1, eM1, eMid, eF, eV;
    static int inited = 0;
    if (!inited) {
        cudaStreamCreateWithFlags(&s1, cudaStreamNonBlocking);
        cudaStreamCreateWithFlags(&s2, cudaStreamNonBlocking);
        cudaStreamCreateWithFlags(&s3, cudaStreamNonBlocking);
        cudaEventCreateWithFlags(&eRoot,  cudaEventDisableTiming);
        cudaEventCreateWithFlags(&eConv,  cudaEventDisableTiming);
        cudaEventCreateWithFlags(&eSetup, cudaEventDisableTiming);
        cudaEventCreateWithFlags(&eL,     cudaEventDisableTiming);
        cudaEventCreateWithFlags(&eG,     cudaEventDisableTiming);
        cudaEventCreateWithFlags(&eB1,    cudaEventDisableTiming);
        cudaEventCreateWithFlags(&eM1,    cudaEventDisableTiming);
        cudaEventCreateWithFlags(&eMid,   cudaEventDisableTiming);
        cudaEventCreateWithFlags(&eF,     cudaEventDisableTiming);
        cudaEventCreateWithFlags(&eV,     cudaEventDisableTiming);
        inited = 1;
    }

    cudaEventRecord(eRoot, 0);

    // ---- s1: conv -> zM -> scoresM(+max) ----
    cudaStreamWaitEvent(s1, eRoot, 0);
    k_conv<<<(WTOT + 255)/256, 256, 0, s1>>>(x, Wl, Wm, Wg, Wq, Wk, Wv, Wo, Wf);
    cudaEventRecord(eConv, s1);
    k_hgemm2<<<dim3(2, 32, 4), 256, 0, s1>>>(xhp, DD, 0, whp + WOFF_M, DD, (long)DD*DD, 0,
                                      nullptr, (float*)0, 0, 0, zhp + (long)NN*1024, 1024, 256, DD);
    k_scores<<<(HH*NN)/8, 256, 0, s1>>>(1, ams, amd);

    // ---- s2: zL -> scoresL -> (setup) local gather ----
    cudaStreamWaitEvent(s2, eConv, 0);
    k_hgemm2<<<dim3(2, 32, 4), 256, 0, s2>>>(xhp, DD, 0, whp + WOFF_L, DD, (long)DD*DD, 0,
                                      nullptr, (float*)0, 0, 0, zhp, 1024, 256, DD);
    k_scores<<<(HH*NN)/8, 256, 0, s2>>>(0, als, ald);

    // ---- s3: zG -> scoresG -> sort -> prefix -> global ----
    cudaStreamWaitEvent(s3, eConv, 0);
    k_hgemm2<<<dim3(2, 32, 4), 256, 0, s3>>>(xhp, DD, 0, whp + WOFF_G, DD, (long)DD*DD, 0,
                                      nullptr, (float*)0, 0, 0, zhp + 2L*NN*1024, 1024, 256, DD);
    k_scores<<<(HH*NN)/8, 256, 0, s3>>>(2, ags, agd);
    k_sort<<<HH, 1024, 0, s3>>>();
    k_prefA<<<HH*32, 256, 0, s3>>>();
    k_prefB<<<HH, 256, 0, s3>>>();
    k_global<<<NN, 256, 0, s3>>>(bg);
    cudaEventRecord(eG, s3);

    // ---- stream 0: graph mask setup ----
    k_detect<<<1, 32>>>((const unsigned*)edges);
    k_clear<<<(NN*NW + 255)/256, 256>>>();
    k_edges<<<(EE + 255)/256, 256>>>(edges);
    k_eye_ml<<<(NN + 255)/256, 256>>>();
    k_twohop<<<NN, NW>>>();
    k_transpose<<<2048, 256>>>();
    k_mm<<<NN, NW>>>();
    cudaEventRecord(eSetup, 0);

    // ---- stream 0: q projection ----
    cudaStreamWaitEvent(0, eConv, 0);
    k_hgemm2<<<dim3(2, 32, 1), 256>>>(xhp, DD, 0, whp + WOFF_Q, DD, 0, 0, bq,
                                      qp, DD, 0, (__half*)0, 0, 0, DD);

    // ---- s1: buildP half1 -> eB1 -> buildP half2 -> pgemm half2 ----
    cudaStreamWaitEvent(s1, eSetup, 0);
    k_buildP<<<dim3(128, 4), 256, 0, s1>>>(0);
    cudaEventRecord(eB1, s1);
    k_buildP<<<dim3(128, 4), 256, 0, s1>>>(2048);
    k_pgemm<<<dim3(2, 32, 8), 128, 0, s1>>>(2048);

    // ---- stream 0: pgemm half1 (overlaps buildP half2) ----
    cudaStreamWaitEvent(0, eB1, 0);
    k_pgemm<<<dim3(2, 32, 8), 128>>>(0);
    cudaEventRecord(eM1, 0);

    // ---- s1: midcomb after both pgemm halves ----
    cudaStreamWaitEvent(s1, eM1, 0);
    k_midcomb<<<NN, 256, 0, s1>>>(bm);
    cudaEventRecord(eMid, s1);

    // ---- s2: local gather ----
    cudaStreamWaitEvent(s2, eSetup, 0);
    k_agg2<<<NN, 256, 0, s2>>>(0, mlp, bl, cathp + 0, 768);
    cudaEventRecord(eL, s2);

    // ---- s2: fusion MLP (needs full cath) ----
    cudaStreamWaitEvent(s2, eMid, 0);
    cudaStreamWaitEvent(s2, eG, 0);
    k_hgemm2<<<dim3(2, 32, 1), 256, 0, s2>>>(cathp, 768, 0, whp + WOFF_F, 3*DD, 0, 0, bfv,
                                      hp, DD, 0, (__half*)0, 0, 0, 3*DD);
    cudaEventRecord(eF, s2);

    // ---- s3: v projection (needs full cath) ----
    cudaStreamWaitEvent(s3, eL, 0);
    cudaStreamWaitEvent(s3, eMid, 0);
    k_hgemm2<<<dim3(2, 32, 3), 256, 0, s3>>>(cathp, 768, 256, whp + WOFF_V, DD, 0, 0, bv,
                                      vp, DD, (long)NN*DD, (__half*)0, 0, 0, DD);
    cudaEventRecord(eV, s3);

    // ---- stream 0: k projection + attention + output proj ----
    cudaStreamWaitEvent(0, eL, 0);
    cudaStreamWaitEvent(0, eMid, 0);
    cudaStreamWaitEvent(0, eG, 0);
    k_hgemm2<<<dim3(2, 32, 3), 256>>>(cathp, 768, 256, whp + WOFF_K, DD, 0, 0, bk,
                                      kp, DD, (long)NN*DD, (__half*)0, 0, 0, DD);
    cudaStreamWaitEvent(0, eV, 0);
    k_attn<<<NN, 128>>>();
    k_hgemm2<<<dim3(2, 32, 1), 256>>>(atthp, DD, 0, whp + WOFF_O, DD, 0, 0, bo,
                                      xattp, DD, 0, (__half*)0, 0, 0, DD);

    // ---- join + final ----
    cudaStreamWaitEvent(0, eF, 0);
    k_final<<<NN, 256>>>(lng, lnb, out);
}

// round 17
// speedup vs baseline: 1.0817x; 1.0393x over previous
#include <cuda_runtime.h>
#include <cuda_fp16.h>
#include <mma.h>
#include <math.h>
#include <stdint.h>

using namespace nvcuda;

#define NN 4096
#define DD 256
#define HH 4
#define DHH 64
#define EE 65536
#define NW 128
#define LNEPS 1e-5f

// ---------------- device scratch ----------------
__device__ int      g_is64;
__device__ unsigned g_A   [NN*NW];
__device__ unsigned g_ML  [NN*NW];
__device__ unsigned g_UND [NN*NW];
__device__ unsigned g_UNDT[NN*NW];
__device__ unsigned g_MM  [NN*NW];

__device__ __half g_zh  [3L*NN*HH*DD];     // [sc][n][h*256+d] fp16
__device__ __half g_xh  [NN*DD];
__device__ __half g_wh  [3*HH*DD*DD + 4*DD*DD + DD*3*DD];
__device__ __half g_P   [4L*NN*NN];        // mid attention matrix per head
__device__ float  g_den [HH*NN];
__device__ float  g_part [HH*NN*DD];
__device__ float  g_part2[HH*NN*DD];
__device__ unsigned g_maxu[HH];

__device__ float g_ssrc[3*HH*NN];
__device__ float g_F1  [3*HH*NN];
__device__ float g_F2  [3*HH*NN];
__device__ float g_T   [3*HH*NN];
__device__ float g_E1  [3*HH*NN];
__device__ float g_E2  [3*HH*NN];

__device__ __half g_cath[NN*3*DD];
__device__ float g_sorted[HH*NN];
__device__ int   g_perm  [HH*NN];
__device__ float g_P1[HH*NN*DD];
__device__ float g_P2[HH*NN*DD];
__device__ float g_C1[HH*NN];
__device__ float g_C2[HH*NN];
__device__ float g_T1[HH*32*DD], g_T2[HH*32*DD];
__device__ float g_O1[HH*33*DD], g_O2[HH*33*DD];
__device__ float g_TC1[HH*32], g_TC2[HH*32];
__device__ float g_OC1[HH*33], g_OC2[HH*33];

__device__ float  g_q   [NN*DD];
__device__ float  g_k3  [3*NN*DD];
__device__ float  g_v3  [3*NN*DD];
__device__ __half g_atth[NN*DD];
__device__ float  g_xatt[NN*DD];
__device__ float  g_hbuf[NN*DD];

#define WOFF_L  0
#define WOFF_M  262144
#define WOFF_G  524288
#define WOFF_Q  786432
#define WOFF_K  851968
#define WOFF_V  917504
#define WOFF_O  983040
#define WOFF_F  1048576
#define WTOT    1245184

// monotonic float<->uint ordering
__device__ __forceinline__ unsigned fkey(float f) {
    unsigned u = __float_as_uint(f);
    return (u >> 31) ? ~u : (u | 0x80000000u);
}
__device__ __forceinline__ float fdec(unsigned k) {
    unsigned u = (k >> 31) ? (k & 0x7fffffffu) : ~k;
    return __uint_as_float(u);
}

__device__ __forceinline__ void cp16(uint32_t dst, const void* src) {
    asm volatile("cp.async.cg.shared.global [%0], [%1], 16;" :: "r"(dst), "l"(src));
}
#define CP_COMMIT() asm volatile("cp.async.commit_group;" ::: "memory")
#define CP_WAIT0()  asm volatile("cp.async.wait_group 0;" ::: "memory")

// ---------------- setup kernels ----------------
__global__ void k_detect(const unsigned* e) {
    if (threadIdx.x == 0) {
        int all0 = 1;
        for (int i = 0; i < 128; i++) if (e[2*i+1] != 0u) { all0 = 0; break; }
        g_is64 = all0;
    }
}

__global__ void k_clear() {
    int i = blockIdx.x * blockDim.x + threadIdx.x;
    if (i < NN*NW) { g_A[i] = 0u; g_ML[i] = 0u; }
}

__global__ void k_edges(const int* e) {
    int i = blockIdx.x * blockDim.x + threadIdx.x;
    if (i >= EE) return;
    int s, t;
    if (g_is64) { s = e[2*i]; t = e[2*(EE+i)]; }
    else        { s = e[i];   t = e[EE+i];     }
    atomicOr(&g_A [s*NW + (t>>5)], 1u << (t & 31));
    atomicOr(&g_ML[t*NW + (s>>5)], 1u << (s & 31));
}

__global__ void k_eye_ml() {
    int i = blockIdx.x * blockDim.x + threadIdx.x;
    if (i < NN) g_ML[i*NW + (i>>5)] |= 1u << (i & 31);
}

__global__ void k_twohop() {
    int i = blockIdx.x, w = threadIdx.x;
    __shared__ unsigned sh[NW];
    sh[w] = g_A[i*NW + w];
    __syncthreads();
    unsigned acc = sh[w];
    for (int w2 = 0; w2 < NW; w2++) {
        unsigned bits = sh[w2];
        while (bits) {
            int b = __ffs(bits) - 1; bits &= bits - 1;
            acc |= g_A[((w2<<5)+b)*NW + w];
        }
    }
    g_UND[i*NW + w] = acc;
}

__global__ void k_transpose() {
    int tile = blockIdx.x * 8 + (threadIdx.x >> 5);
    int lane = threadIdx.x & 31;
    int ti = tile >> 7, tj = tile & 127;
    __shared__ unsigned sm[8][32];
    int wslot = threadIdx.x >> 5;
    sm[wslot][lane] = g_UND[(ti*32 + lane)*NW + tj];
    __syncwarp();
    unsigned y = 0;
    #pragma unroll
    for (int b = 0; b < 32; b++) y |= ((sm[wslot][b] >> lane) & 1u) << b;
    g_UNDT[(tj*32 + lane)*NW + ti] = y;
}

__global__ void k_mm() {
    int i = blockIdx.x, w = threadIdx.x;
    unsigned res = g_UND[i*NW + w] | g_UNDT[i*NW + w];
    if (w == (i >> 5)) res |= 1u << (i & 31);
    g_MM[i*NW + w] = res;
}

__global__ void k_conv(const float* __restrict__ x,
                       const float* Wl, const float* Wm, const float* Wg,
                       const float* Wq, const float* Wk, const float* Wv,
                       const float* Wo, const float* Wf) {
    int i = blockIdx.x * blockDim.x + threadIdx.x;
    if (i < 4) g_maxu[i] = 0u;
    if (i < NN*DD) g_xh[i] = __float2half(x[i]);
    if (i < WTOT) {
        float v;
        if      (i < WOFF_M) v = Wl[i - WOFF_L];
        else if (i < WOFF_G) v = Wm[i - WOFF_M];
        else if (i < WOFF_Q) v = Wg[i - WOFF_G];
        else if (i < WOFF_K) v = Wq[i - WOFF_Q];
        else if (i < WOFF_V) v = Wk[i - WOFF_K];
        else if (i < WOFF_O) v = Wv[i - WOFF_V];
        else if (i < WOFF_F) v = Wo[i - WOFF_O];
        else                 v = Wf[i - WOFF_F];
        g_wh[i] = __float2half(v);
    }
}

// ---------------- 128x128 double-buffered wmma GEMM (projections) ----------------
__global__ __launch_bounds__(256, 2)
void k_hgemm2(const __half* __restrict__ A, int lda, long sA,
              const __half* __restrict__ B, int ldb, long sB, int brm,
              const float* __restrict__ bias,
              float* __restrict__ Cf, int ldc, long sC,
              __half* Ch, int ldch, long sCh, int K) {
    int bz = blockIdx.z;
    const __half* Ae = A + (long)bz * sA;
    const __half* Be = B + (long)bz * sB;
    float* cf = Cf ? Cf + (long)bz * sC : (float*)0;
    __half* ch = Ch ? Ch + (long)bz * sCh : (__half*)0;
    int bm = blockIdx.y << 7;
    int bn = blockIdx.x << 7;
    int tid = threadIdx.x;
    int wid = tid >> 5, lane = tid & 31;
    int wm = wid >> 2, wn = wid & 3;

    __shared__ __half As[2][5120];
    __shared__ __half Bs[2][5120];

    wmma::fragment<wmma::accumulator,16,16,16,float> acc[4][2];
    #pragma unroll
    for (int i = 0; i < 4; i++)
        #pragma unroll
        for (int j = 0; j < 2; j++) wmma::fill_fragment(acc[i][j], 0.f);

    int KT = K >> 5;
    int i0 = tid*2, i1 = tid*2 + 1;

    {
        int r0 = i0>>2, s0 = i0&3, r1 = i1>>2, s1 = i1&3;
        *(uint4*)&As[0][r0*40 + s0*8] = *(const uint4*)&Ae[(long)(bm+r0)*lda + s0*8];
        *(uint4*)&As[0][r1*40 + s1*8] = *(const uint4*)&Ae[(long)(bm+r1)*lda + s1*8];
        if (brm) {
            int br0 = i0>>4, bs0 = i0&15, br1 = i1>>4, bs1 = i1&15;
            *(uint4*)&Bs[0][br0*144 + bs0*8] = *(const uint4*)&Be[(long)br0*ldb + bn + bs0*8];
            *(uint4*)&Bs[0][br1*144 + bs1*8] = *(const uint4*)&Be[(long)br1*ldb + bn + bs1*8];
        } else {
            *(uint4*)&Bs[0][r0*40 + s0*8] = *(const uint4*)&Be[(long)(bn+r0)*ldb + s0*8];
            *(uint4*)&Bs[0][r1*40 + s1*8] = *(const uint4*)&Be[(long)(bn+r1)*ldb + s1*8];
        }
    }
    __syncthreads();

    int buf = 0;
    for (int kt = 0; kt < KT; kt++) {
        uint4 pa0, pa1, pb0, pb1;
        int havenext = (kt + 1 < KT);
        int k0n = (kt + 1) << 5;
        int r0 = i0>>2, s0 = i0&3, r1 = i1>>2, s1 = i1&3;
        int br0 = i0>>4, bs0 = i0&15, br1 = i1>>4, bs1 = i1&15;
        if (havenext) {
            pa0 = *(const uint4*)&Ae[(long)(bm+r0)*lda + k0n + s0*8];
            pa1 = *(const uint4*)&Ae[(long)(bm+r1)*lda + k0n + s1*8];
            if (brm) {
                pb0 = *(const uint4*)&Be[(long)(k0n+br0)*ldb + bn + bs0*8];
                pb1 = *(const uint4*)&Be[(long)(k0n+br1)*ldb + bn + bs1*8];
            } else {
                pb0 = *(const uint4*)&Be[(long)(bn+r0)*ldb + k0n + s0*8];
                pb1 = *(const uint4*)&Be[(long)(bn+r1)*ldb + k0n + s1*8];
            }
        }
        #pragma unroll
        for (int kk = 0; kk < 2; kk++) {
            wmma::fragment<wmma::matrix_a,16,16,16,__half,wmma::row_major> af[4];
            #pragma unroll
            for (int i = 0; i < 4; i++)
                wmma::load_matrix_sync(af[i], &As[buf][(wm*64 + i*16)*40 + kk*16], 40);
            if (brm) {
                wmma::fragment<wmma::matrix_b,16,16,16,__half,wmma::row_major> bf[2];
                #pragma unroll
                for (int j = 0; j < 2; j++)
                    wmma::load_matrix_sync(bf[j], &Bs[buf][kk*16*144 + wn*32 + j*16], 144);
                #pragma unroll
                for (int i = 0; i < 4; i++)
                    #pragma unroll
                    for (int j = 0; j < 2; j++)
                        wmma::mma_sync(acc[i][j], af[i], bf[j], acc[i][j]);
            } else {
                wmma::fragment<wmma::matrix_b,16,16,16,__half,wmma::col_major> bf[2];
                #pragma unroll
                for (int j = 0; j < 2; j++)
                    wmma::load_matrix_sync(bf[j], &Bs[buf][(wn*32 + j*16)*40 + kk*16], 40);
                #pragma unroll
                for (int i = 0; i < 4; i++)
                    #pragma unroll
                    for (int j = 0; j < 2; j++)
                        wmma::mma_sync(acc[i][j], af[i], bf[j], acc[i][j]);
            }
        }
        if (havenext) {
            *(uint4*)&As[buf^1][r0*40 + s0*8] = pa0;
            *(uint4*)&As[buf^1][r1*40 + s1*8] = pa1;
            if (brm) {
                *(uint4*)&Bs[buf^1][br0*144 + bs0*8] = pb0;
                *(uint4*)&Bs[buf^1][br1*144 + bs1*8] = pb1;
            } else {
                *(uint4*)&Bs[buf^1][r0*40 + s0*8] = pb0;
                *(uint4*)&Bs[buf^1][r1*40 + s1*8] = pb1;
            }
        }
        __syncthreads();
        buf ^= 1;
    }

    float* scratch = (float*)&As[0][0] + wid * 320;
    int er = lane >> 1, ec = (lane & 1) * 8;
    #pragma unroll
    for (int i = 0; i < 4; i++) {
        #pragma unroll
        for (int j = 0; j < 2; j++) {
            wmma::store_matrix_sync(scratch, acc[i][j], 20, wmma::mem_row_major);
            __syncwarp();
            int m = bm + wm*64 + i*16 + er;
            int n = bn + wn*32 + j*16 + ec;
            float4 v0 = *(float4*)&scratch[er*20 + ec];
            float4 v1 = *(float4*)&scratch[er*20 + ec + 4];
            if (bias) {
                v0.x += bias[n];   v0.y += bias[n+1]; v0.z += bias[n+2]; v0.w += bias[n+3];
                v1.x += bias[n+4]; v1.y += bias[n+5]; v1.z += bias[n+6]; v1.w += bias[n+7];
            }
            if (cf) {
                *(float4*)&cf[(long)m*ldc + n]     = v0;
                *(float4*)&cf[(long)m*ldc + n + 4] = v1;
            }
            if (ch) {
                __half2 h0 = __floats2half2_rn(v0.x, v0.y);
                __half2 h1 = __floats2half2_rn(v0.z, v0.w);
                __half2 h2 = __floats2half2_rn(v1.x, v1.y);
                __half2 h3 = __floats2half2_rn(v1.z, v1.w);
                uint4 pk;
                pk.x = *(unsigned*)&h0; pk.y = *(unsigned*)&h1;
                pk.z = *(unsigned*)&h2; pk.w = *(unsigned*)&h3;
                *(uint4*)&ch[(long)m*ldch + n] = pk;
            }
            __syncwarp();
        }
    }
}

// ---------------- P@z GEMM: 128-thread blocks, cp.async, split-K=2 ----------------
// grid (2, 64, 8): bn (128 cols), bm (64 rows), bz = head*2 + ks. 4 warps.
__global__ __launch_bounds__(128)
void k_pgemm() {
    int bz = blockIdx.z;
    int h  = bz >> 1;
    int ks = bz & 1;
    int koff = ks << 11;                 // 0 or 2048
    const __half* Ae = g_P + (long)h*NN*NN;
    const __half* Be = g_zh + (long)NN*1024 + h*256;
    float* cf = (ks ? g_part2 : g_part) + (long)h*NN*DD;
    int bm = blockIdx.y << 6;
    int bn = blockIdx.x << 7;
    int tid = threadIdx.x;
    int wid = tid >> 5, lane = tid & 31;

    __shared__ __half As[2][64*40];
    __shared__ __half Bs[2][32*136];

    wmma::fragment<wmma::accumulator,16,16,16,float> acc[4][2];
    #pragma unroll
    for (int i = 0; i < 4; i++)
        #pragma unroll
        for (int j = 0; j < 2; j++) wmma::fill_fragment(acc[i][j], 0.f);

    int ua0 = tid*2, ua1 = tid*2 + 1;
    int ar0 = ua0 >> 2, as0 = ua0 & 3, ar1 = ua1 >> 2, as1 = ua1 & 3;

    {
        int k0 = koff;
        cp16((uint32_t)__cvta_generic_to_shared(&As[0][ar0*40 + as0*8]),
             &Ae[(long)(bm+ar0)*NN + k0 + as0*8]);
        cp16((uint32_t)__cvta_generic_to_shared(&As[0][ar1*40 + as1*8]),
             &Ae[(long)(bm+ar1)*NN + k0 + as1*8]);
        #pragma unroll
        for (int t = 0; t < 4; t++) {
            int u = tid*4 + t;
            int br = u >> 4, bs = u & 15;
            cp16((uint32_t)__cvta_generic_to_shared(&Bs[0][br*136 + bs*8]),
                 &Be[(long)(k0+br)*1024 + bn + bs*8]);
        }
        CP_COMMIT();
        CP_WAIT0();
    }
    __syncthreads();

    int buf = 0;
    for (int kt = 0; kt < 64; kt++) {
        if (kt + 1 < 64) {
            int k0 = koff + ((kt + 1) << 5);
            cp16((uint32_t)__cvta_generic_to_shared(&As[buf^1][ar0*40 + as0*8]),
                 &Ae[(long)(bm+ar0)*NN + k0 + as0*8]);
            cp16((uint32_t)__cvta_generic_to_shared(&As[buf^1][ar1*40 + as1*8]),
                 &Ae[(long)(bm+ar1)*NN + k0 + as1*8]);
            #pragma unroll
            for (int t = 0; t < 4; t++) {
                int u = tid*4 + t;
                int br = u >> 4, bs = u & 15;
                cp16((uint32_t)__cvta_generic_to_shared(&Bs[buf^1][br*136 + bs*8]),
                     &Be[(long)(k0+br)*1024 + bn + bs*8]);
            }
            CP_COMMIT();
        }
        #pragma unroll
        for (int kk = 0; kk < 2; kk++) {
            wmma::fragment<wmma::matrix_a,16,16,16,__half,wmma::row_major> af[4];
            #pragma unroll
            for (int i = 0; i < 4; i++)
                wmma::load_matrix_sync(af[i], &As[buf][(i*16)*40 + kk*16], 40);
            wmma::fragment<wmma::matrix_b,16,16,16,__half,wmma::row_major> bf[2];
            #pragma unroll
            for (int j = 0; j < 2; j++)
                wmma::load_matrix_sync(bf[j], &Bs[buf][kk*16*136 + wid*32 + j*16], 136);
            #pragma unroll
            for (int i = 0; i < 4; i++)
                #pragma unroll
                for (int j = 0; j < 2; j++)
                    wmma::mma_sync(acc[i][j], af[i], bf[j], acc[i][j]);
        }
        CP_WAIT0();
        __syncthreads();
        buf ^= 1;
    }

    float* scratch = (float*)&As[0][0] + wid * 320;
    int er = lane >> 1, ec = (lane & 1) * 8;
    #pragma unroll
    for (int i = 0; i < 4; i++) {
        #pragma unroll
        for (int j = 0; j < 2; j++) {
            wmma::store_matrix_sync(scratch, acc[i][j], 20, wmma::mem_row_major);
            __syncwarp();
            int m = bm + i*16 + er;
            int n = bn + wid*32 + j*16 + ec;
            *(float4*)&cf[(long)m*DD + n]     = *(float4*)&scratch[er*20 + ec];
            *(float4*)&cf[(long)m*DD + n + 4] = *(float4*)&scratch[er*20 + ec + 4];
            __syncwarp();
        }
    }
}

// ---------------- attention scalars, per scale (sc==1 also folds row max) ----------------
__global__ void k_scores(int sc, const float* __restrict__ as, const float* __restrict__ ad) {
    int item = blockIdx.x * 8 + (threadIdx.x >> 5);
    int lane = threadIdx.x & 31;
    if (item >= HH*NN) return;
    int n = item & (NN - 1);
    int h = item >> 12;
    int gi = sc*HH*NN + item;
    const __half* zr = g_zh + ((long)sc*NN + n)*1024 + h*DD;
    float s1 = 0.f, s2 = 0.f;
    for (int d0 = lane; d0 < DD; d0 += 32) {
        float zv = __half2float(zr[d0]);
        s1 += zv * as[h*DD + d0];
        s2 += zv * ad[h*DD + d0];
    }
    #pragma unroll
    for (int o = 16; o; o >>= 1) {
        s1 += __shfl_down_sync(0xffffffffu, s1, o);
        s2 += __shfl_down_sync(0xffffffffu, s2, o);
    }
    if (lane == 0) {
        g_ssrc[gi] = s1; g_F1[gi] = expf(s1);  g_F2[gi] = expf(0.2f * s1);
        g_T[gi] = -s2;   g_E1[gi] = expf(s2);  g_E2[gi] = expf(0.2f * s2);
        if (sc == 1) atomicMax(&g_maxu[h], fkey(s1));
    }
}

// ---------------- LOCAL sparse gather ----------------
__global__ void k_agg2(int sc, const unsigned* __restrict__ M,
                       const float* __restrict__ bias,
                       __half* __restrict__ out, int ldo) {
    int i = blockIdx.x, tid = threadIdx.x;
    __shared__ int   s_idx[NN];
    __shared__ float s_w[64][4];
    __shared__ int   s_cntw[NW], s_off[NW + 1];
    __shared__ float s_t[4], s_e1[4], s_e2[4];
    __shared__ float s_acc[2][4][32][8];
    __shared__ float s_den[2][4];
    if (tid < 4) {
        int id = (sc*4 + tid) * NN + i;
        s_t[tid] = g_T[id]; s_e1[tid] = g_E1[id]; s_e2[tid] = g_E2[id];
    }
    if (tid < NW) s_cntw[tid] = __popc(M[i*NW + tid]);
    __syncthreads();
    if (tid == 0) {
        int a = 0;
        for (int w = 0; w < NW; w++) { s_off[w] = a; a += s_cntw[w]; }
        s_off[NW] = a;
    }
    __syncthreads();
    if (tid < NW) {
        unsigned bits = M[i*NW + tid];
        int p = s_off[tid];
        while (bits) { int b = __ffs(bits) - 1; bits &= bits - 1; s_idx[p++] = (tid<<5) + b; }
    }
    __syncthreads();
    int deg = s_off[NW];
    int grp = tid >> 7;
    int t2  = tid & 127;
    int h   = t2 >> 5;
    int slot = t2 & 31;
    const uint4* zh = (const uint4*)(g_zh + (long)sc*NN*1024);
    float acc[8] = {0,0,0,0,0,0,0,0};
    float den = 0.f;
    int jw = tid & 63, hw = tid >> 6;
    for (int base = 0; base < deg; base += 64) {
        int cnt = min(64, deg - base);
        if (jw < cnt) {
            int j = s_idx[base + jw];
            int id = (sc*4 + hw) * NN + j;
            float sj = g_ssrc[id];
            s_w[jw][hw] = (sj > s_t[hw]) ? s_e1[hw] * g_F1[id] : s_e2[hw] * g_F2[id];
        }
        __syncthreads();
        for (int q = grp; q < cnt; q += 2) {
            int j = s_idx[base + q];
            uint4 zv = zh[(long)j * 128 + h*32 + slot];
            float w = s_w[q][h];
            den += w;
            __half2 p0 = *(__half2*)&zv.x, p1 = *(__half2*)&zv.y;
            __half2 p2 = *(__half2*)&zv.z, p3 = *(__half2*)&zv.w;
            float2 f0 = __half22float2(p0), f1 = __half22float2(p1);
            float2 f2 = __half22float2(p2), f3 = __half22float2(p3);
            acc[0] += w*f0.x; acc[1] += w*f0.y;
            acc[2] += w*f1.x; acc[3] += w*f1.y;
            acc[4] += w*f2.x; acc[5] += w*f2.y;
            acc[6] += w*f3.x; acc[7] += w*f3.y;
        }
        __syncthreads();
    }
    #pragma unroll
    for (int k = 0; k < 8; k++) s_acc[grp][h][slot][k] = acc[k];
    if (slot == 0) s_den[grp][h] = den;
    __syncthreads();
    int c = tid;
    float m = 0.f;
    #pragma unroll
    for (int hh2 = 0; hh2 < 4; hh2++) {
        float d = s_den[0][hh2] + s_den[1][hh2];
        float v = s_acc[0][hh2][c>>3][c&7] + s_acc[1][hh2][c>>3][c&7];
        m += v / d;
    }
    out[(long)i * ldo + c] = __float2half(fmaxf(0.25f * m + bias[c], 0.f));
}

// ---------------- MID: dense P build + combine ----------------
__global__ void k_buildP() {
    int grp = blockIdx.x, h = blockIdx.y;
    int tid = threadIdx.x;
    int row0 = grp * 16;
    int base = (4 + h) * NN;
    __shared__ float sf1[256], sf2[256], ssj[256];
    __shared__ unsigned smask[16][8];
    __shared__ float ra[16], rb[16], rt[16];
    __shared__ float sred[256];
    if (tid < 16) {
        int i = row0 + tid;
        float t = g_T[base + i];
        float sdst = -t;
        float m = sdst + fdec(g_maxu[h]);
        m = m > 0.f ? m : 0.2f * m;
        ra[tid] = expf(sdst - m);
        rb[tid] = expf(0.2f * sdst - m);
        rt[tid] = t;
    }
    float dsum[16];
    #pragma unroll
    for (int r = 0; r < 16; r++) dsum[r] = 0.f;
    __syncthreads();
    for (int c0 = 0; c0 < NN; c0 += 256) {
        sf1[tid] = g_F1[base + c0 + tid];
        sf2[tid] = g_F2[base + c0 + tid];
        ssj[tid] = g_ssrc[base + c0 + tid];
        if (tid < 128) smask[tid>>3][tid&7] = g_MM[(row0 + (tid>>3))*NW + (c0>>5) + (tid&7)];
        __syncthreads();
        float f1 = sf1[tid], f2 = sf2[tid], sj = ssj[tid];
        int wd = tid >> 5; unsigned bm = 1u << (tid & 31);
        long pbase = ((long)h*NN + row0)*NN + c0 + tid;
        #pragma unroll
        for (int r = 0; r < 16; r++) {
            float w = 0.f;
            if (smask[r][wd] & bm)
                w = (sj > rt[r]) ? ra[r]*f1 : rb[r]*f2;
            dsum[r] += w;
            g_P[pbase + (long)r*NN] = __float2half(w);
        }
        __syncthreads();
    }
    for (int r = 0; r < 16; r++) {
        sred[tid] = dsum[r]; __syncthreads();
        for (int o = 128; o; o >>= 1) { if (tid < o) sred[tid] += sred[tid+o]; __syncthreads(); }
        if (tid == 0) g_den[h*NN + row0 + r] = sred[0];
        __syncthreads();
    }
}

__global__ void k_midcomb(const float* __restrict__ bias) {
    int i = blockIdx.x, c = threadIdx.x;
    __shared__ float rden[4];
    if (c < 4) rden[c] = 1.f / g_den[c*NN + i];
    __syncthreads();
    float m = 0.f;
    #pragma unroll
    for (int h = 0; h < 4; h++) {
        long idx = ((long)h*NN + i)*DD + c;
        m = fmaf(g_part[idx] + g_part2[idx], rden[h], m);
    }
    g_cath[(long)i*768 + 256 + c] = __float2half(fmaxf(0.25f * m + bias[c], 0.f));
}

// ---------------- global scale ----------------
__global__ void k_sort() {
    int h = blockIdx.x, tid = threadIdx.x;
    __shared__ float key[NN];
    __shared__ int   idx[NN];
    for (int i = tid; i < NN; i += 1024) { key[i] = g_ssrc[(8 + h)*NN + i]; idx[i] = i; }
    __syncthreads();
    for (int k = 2; k <= NN; k <<= 1) {
        for (int j = k >> 1; j > 0; j >>= 1) {
            for (int i = tid; i < NN; i += 1024) {
                int ixj = i ^ j;
                if (ixj > i) {
                    bool up = (i & k) == 0;
                    float a = key[i], b = key[ixj];
                    if ((a > b) == up) {
                        key[i] = b; key[ixj] = a;
                        int t = idx[i]; idx[i] = idx[ixj]; idx[ixj] = t;
                    }
                }
            }
            __syncthreads();
        }
    }
    for (int i = tid; i < NN; i += 1024) { g_sorted[h*NN + i] = key[i]; g_perm[h*NN + i] = idx[i]; }
}

__global__ void k_prefA() {
    int h = blockIdx.x >> 5, k = blockIdx.x & 31;
    int c = threadIdx.x;
    int base = (8 + h) * NN;
    float a1 = 0.f, a2 = 0.f, c1 = 0.f, c2 = 0.f;
    int r0 = k << 7;
    for (int l = 0; l < 128; l++) {
        int r = r0 + l;
        int j = g_perm[h*NN + r];
        float f1 = g_F1[base + j], f2 = g_F2[base + j];
        float zv = __half2float(g_zh[((long)2*NN + j)*1024 + h*DD + c]);
        a1 += f1 * zv; a2 += f2 * zv;
        g_P1[((long)h*NN + r)*DD + c] = a1;
        g_P2[((long)h*NN + r)*DD + c] = a2;
        if (c == 0) { c1 += f1; c2 += f2; g_C1[h*NN + r] = c1; g_C2[h*NN + r] = c2; }
    }
    g_T1[(h*32 + k)*DD + c] = a1;
    g_T2[(h*32 + k)*DD + c] = a2;
    if (c == 0) { g_TC1[h*32 + k] = c1; g_TC2[h*32 + k] = c2; }
}

__global__ void k_prefB() {
    int h = blockIdx.x, c = threadIdx.x;
    float o1 = 0.f, o2 = 0.f;
    for (int k = 0; k < 32; k++) {
        g_O1[(h*33 + k)*DD + c] = o1; g_O2[(h*33 + k)*DD + c] = o2;
        o1 += g_T1[(h*32 + k)*DD + c]; o2 += g_T2[(h*32 + k)*DD + c];
    }
    g_O1[(h*33 + 32)*DD + c] = o1; g_O2[(h*33 + 32)*DD + c] = o2;
    if (c == 0) {
        float oc1 = 0.f, oc2 = 0.f;
        for (int k = 0; k < 32; k++) {
            g_OC1[h*33 + k] = oc1; g_OC2[h*33 + k] = oc2;
            oc1 += g_TC1[h*32 + k]; oc2 += g_TC2[h*32 + k];
        }
        g_OC1[h*33 + 32] = oc1; g_OC2[h*33 + 32] = oc2;
    }
}

__global__ void k_global(const float* __restrict__ bias) {
    int i = blockIdx.x, tid = threadIdx.x;
    __shared__ int   s_r[4], s_kc[4];
    __shared__ float s_den[4], s_e1[4], s_e2[4];
    if (tid < 4) {
        int h = tid, id = (8 + h)*NN + i;
        float t = g_T[id], e1 = g_E1[id], e2 = g_E2[id];
        const float* key = g_sorted + h*NN;
        int lo = 0, hi = NN;
        while (lo < hi) { int mid = (lo + hi) >> 1; if (key[mid] <= t) lo = mid + 1; else hi = mid; }
        int r = lo;
        float c1 = 0.f, c2 = 0.f; int kc = 0;
        if (r) {
            int idx = r - 1; kc = idx >> 7;
            c1 = g_C1[h*NN + idx] + g_OC1[h*33 + kc];
            c2 = g_C2[h*NN + idx] + g_OC2[h*33 + kc];
        }
        float c1t = g_OC1[h*33 + 32];
        s_r[h] = r; s_kc[h] = kc; s_e1[h] = e1; s_e2[h] = e2;
        s_den[h] = e1 * (c1t - c1) + e2 * c2;
    }
    __syncthreads();
    int c = tid; float m = 0.f;
    #pragma unroll
    for (int h = 0; h < 4; h++) {
        int r = s_r[h];
        float p1 = 0.f, p2 = 0.f;
        if (r) {
            int idx = r - 1, kc = s_kc[h];
            p1 = g_P1[((long)h*NN + idx)*DD + c] + g_O1[(h*33 + kc)*DD + c];
            p2 = g_P2[((long)h*NN + idx)*DD + c] + g_O2[(h*33 + kc)*DD + c];
        }
        float t1 = g_O1[(h*33 + 32)*DD + c];
        float num = s_e1[h] * (t1 - p1) + s_e2[h] * p2;
        m += num / s_den[h];
    }
    m = 0.25f * m + bias[c];
    g_cath[(long)i*768 + 512 + c] = __float2half(fmaxf(m, 0.f));
}

// ---------------- MHA core ----------------
__global__ void k_attn() {
    int n = blockIdx.x, tid = threadIdx.x;
    int h = tid >> 5, lane = tid & 31;
    const float* qp = g_q + (long)n*DD + h*DHH;
    float s[3];
    #pragma unroll
    for (int sc = 0; sc < 3; sc++) {
        const float* kp = g_k3 + ((long)sc*NN + n)*DD + h*DHH;
        float acc = qp[lane]*kp[lane] + qp[lane+32]*kp[lane+32];
        #pragma unroll
        for (int o = 16; o; o >>= 1) acc += __shfl_xor_sync(0xffffffffu, acc, o);
        s[sc] = acc * 0.125f;
    }
    float mx = fmaxf(s[0], fmaxf(s[1], s[2]));
    float e0 = expf(s[0]-mx), e1 = expf(s[1]-mx), e2 = expf(s[2]-mx);
    float inv = 1.f / (e0 + e1 + e2);
    e0 *= inv; e1 *= inv; e2 *= inv;
    #pragma unroll
    for (int p = 0; p < 2; p++) {
        int d0 = h*DHH + lane + p*32;
        long off = (long)n*DD + d0;
        float v = e0*g_v3[off] + e1*g_v3[(long)NN*DD + off] + e2*g_v3[2L*NN*DD + off];
        g_atth[off] = __float2half(v);
    }
}

// ---------------- LayerNorm + ReLU + residual ----------------
__global__ void k_final(const float* __restrict__ lng, const float* __restrict__ lnb,
                        float* __restrict__ out) {
    int i = blockIdx.x, c = threadIdx.x;
    __shared__ float red[256];
    float v = g_hbuf[(long)i*DD + c];
    red[c] = v; __syncthreads();
    #pragma unroll
    for (int o = 128; o; o >>= 1) { if (c < o) red[c] += red[c+o]; __syncthreads(); }
    float mu = red[0] * (1.f / DD);
    __syncthreads();
    float dv = v - mu;
    red[c] = dv * dv; __syncthreads();
    #pragma unroll
    for (int o = 128; o; o >>= 1) { if (c < o) red[c] += red[c+o]; __syncthreads(); }
    float var = red[0] * (1.f / DD);
    float y = dv * rsqrtf(var + LNEPS) * lng[c] + lnb[c];
    y = fmaxf(y, 0.f);
    out[(long)i*DD + c] = y + g_xatt[(long)i*DD + c];
}

// ---------------- launch (R12 multi-stream fork/join DAG) ----------------
extern "C" void kernel_launch(void* const* d_in, const int* in_sizes, int n_in,
                              void* d_out, int out_size) {
    const float* x    = (const float*)d_in[0];
    const int*   edges= (const int*)  d_in[1];
    const float* Wl   = (const float*)d_in[2];
    const float* als  = (const float*)d_in[3];
    const float* ald  = (const float*)d_in[4];
    const float* bl   = (const float*)d_in[5];
    const float* Wm   = (const float*)d_in[6];
    const float* ams  = (const float*)d_in[7];
    const float* amd  = (const float*)d_in[8];
    const float* bm   = (const float*)d_in[9];
    const float* Wg   = (const float*)d_in[10];
    const float* ags  = (const float*)d_in[11];
    const float* agd  = (const float*)d_in[12];
    const float* bg   = (const float*)d_in[13];
    const float* Wq   = (const float*)d_in[14];
    const float* bq   = (const float*)d_in[15];
    const float* Wk   = (const float*)d_in[16];
    const float* bk   = (const float*)d_in[17];
    const float* Wv   = (const float*)d_in[18];
    const float* bv   = (const float*)d_in[19];
    const float* Wo   = (const float*)d_in[20];
    const float* bo   = (const float*)d_in[21];
    const float* Wf   = (const float*)d_in[22];
    const float* bfv  = (const float*)d_in[23];
    const float* lng  = (const float*)d_in[24];
    const float* lnb  = (const float*)d_in[25];
    float* out = (float*)d_out;

    __half* zhp;    cudaGetSymbolAddress((void**)&zhp,   g_zh);
    __half* xhp;    cudaGetSymbolAddress((void**)&xhp,   g_xh);
    __half* whp;    cudaGetSymbolAddress((void**)&whp,   g_wh);
    __half* cathp;  cudaGetSymbolAddress((void**)&cathp, g_cath);
    float* qp;      cudaGetSymbolAddress((void**)&qp,    g_q);
    float* kp;      cudaGetSymbolAddress((void**)&kp,    g_k3);
    float* vp;      cudaGetSymbolAddress((void**)&vp,    g_v3);
    __half* atthp;  cudaGetSymbolAddress((void**)&atthp, g_atth);
    float* xattp;   cudaGetSymbolAddress((void**)&xattp, g_xatt);
    float* hp;      cudaGetSymbolAddress((void**)&hp,    g_hbuf);
    unsigned* mlp;  cudaGetSymbolAddress((void**)&mlp,   g_ML);

    static cudaStream_t s1, s2, s3;
    static cudaEvent_t eRoot, eConv, eSetup, eL, eMid, eG, eF, eV;
    static int inited = 0;
    if (!inited) {
        cudaStreamCreateWithFlags(&s1, cudaStreamNonBlocking);
        cudaStreamCreateWithFlags(&s2, cudaStreamNonBlocking);
        cudaStreamCreateWithFlags(&s3, cudaStreamNonBlocking);
        cudaEventCreateWithFlags(&eRoot,  cudaEventDisableTiming);
        cudaEventCreateWithFlags(&eConv,  cudaEventDisableTiming);
        cudaEventCreateWithFlags(&eSetup, cudaEventDisableTiming);
        cudaEventCreateWithFlags(&eL,     cudaEventDisableTiming);
        cudaEventCreateWithFlags(&eMid,   cudaEventDisableTiming);
        cudaEventCreateWithFlags(&eG,     cudaEventDisableTiming);
        cudaEventCreateWithFlags(&eF,     cudaEventDisableTiming);
        cudaEventCreateWithFlags(&eV,     cudaEventDisableTiming);
        inited = 1;
    }

    cudaEventRecord(eRoot, 0);

    // ---- s1: conv -> zM -> scoresM(+max) -> (setup) buildP -> P-GEMM -> midcomb ----
    cudaStreamWaitEvent(s1, eRoot, 0);
    k_conv<<<(WTOT + 255)/256, 256, 0, s1>>>(x, Wl, Wm, Wg, Wq, Wk, Wv, Wo, Wf);
    cudaEventRecord(eConv, s1);
    k_hgemm2<<<dim3(2, 32, 4), 256, 0, s1>>>(xhp, DD, 0, whp + WOFF_M, DD, (long)DD*DD, 0,
                                      nullptr, (float*)0, 0, 0, zhp + (long)NN*1024, 1024, 256, DD);
    k_scores<<<(HH*NN)/8, 256, 0, s1>>>(1, ams, amd);

    // ---- s2: zL -> scoresL -> (setup) local gather ----
    cudaStreamWaitEvent(s2, eConv, 0);
    k_hgemm2<<<dim3(2, 32, 4), 256, 0, s2>>>(xhp, DD, 0, whp + WOFF_L, DD, (long)DD*DD, 0,
                                      nullptr, (float*)0, 0, 0, zhp, 1024, 256, DD);
    k_scores<<<(HH*NN)/8, 256, 0, s2>>>(0, als, ald);

    // ---- s3: zG -> scoresG -> sort -> prefix -> global ----
    cudaStreamWaitEvent(s3, eConv, 0);
    k_hgemm2<<<dim3(2, 32, 4), 256, 0, s3>>>(xhp, DD, 0, whp + WOFF_G, DD, (long)DD*DD, 0,
                                      nullptr, (float*)0, 0, 0, zhp + 2L*NN*1024, 1024, 256, DD);
    k_scores<<<(HH*NN)/8, 256, 0, s3>>>(2, ags, agd);
    k_sort<<<HH, 1024, 0, s3>>>();
    k_prefA<<<HH*32, 256, 0, s3>>>();
    k_prefB<<<HH, 256, 0, s3>>>();
    k_global<<<NN, 256, 0, s3>>>(bg);
    cudaEventRecord(eG, s3);

    // ---- stream 0: graph mask setup (parallel) ----
    k_detect<<<1, 32>>>((const unsigned*)edges);
    k_clear<<<(NN*NW + 255)/256, 256>>>();
    k_edges<<<(EE + 255)/256, 256>>>(edges);
    k_eye_ml<<<(NN + 255)/256, 256>>>();
    k_twohop<<<NN, NW>>>();
    k_transpose<<<2048, 256>>>();
    k_mm<<<NN, NW>>>();
    cudaEventRecord(eSetup, 0);

    // ---- stream 0: q projection (needs conv only) ----
    cudaStreamWaitEvent(0, eConv, 0);
    k_hgemm2<<<dim3(2, 32, 1), 256>>>(xhp, DD, 0, whp + WOFF_Q, DD, 0, 0, bq,
                                      qp, DD, 0, (__half*)0, 0, 0, DD);

    // ---- s1 continues: mid dense path (128-thr cp.async P-GEMM) ----
    cudaStreamWaitEvent(s1, eSetup, 0);
    k_buildP<<<dim3(256, 4), 256, 0, s1>>>();
    k_pgemm<<<dim3(2, 64, 8), 128, 0, s1>>>();
    k_midcomb<<<NN, 256, 0, s1>>>(bm);
    cudaEventRecord(eMid, s1);

    // ---- s2 continues: local gather ----
    cudaStreamWaitEvent(s2, eSetup, 0);
    k_agg2<<<NN, 256, 0, s2>>>(0, mlp, bl, cathp + 0, 768);
    cudaEventRecord(eL, s2);

    // ---- s2: fusion MLP (needs full cath) ----
    cudaStreamWaitEvent(s2, eMid, 0);
    cudaStreamWaitEvent(s2, eG, 0);
    k_hgemm2<<<dim3(2, 32, 1), 256, 0, s2>>>(cathp, 768, 0, whp + WOFF_F, 3*DD, 0, 0, bfv,
                                      hp, DD, 0, (__half*)0, 0, 0, 3*DD);
    cudaEventRecord(eF, s2);

    // ---- s3: v projection (needs full cath) ----
    cudaStreamWaitEvent(s3, eL, 0);
    cudaStreamWaitEvent(s3, eMid, 0);
    k_hgemm2<<<dim3(2, 32, 3), 256, 0, s3>>>(cathp, 768, 256, whp + WOFF_V, DD, 0, 0, bv,
                                      vp, DD, (long)NN*DD, (__half*)0, 0, 0, DD);
    cudaEventRecord(eV, s3);

    // ---- stream 0: k projection + attention + output proj ----
    cudaStreamWaitEvent(0, eL, 0);
    cudaStreamWaitEvent(0, eMid, 0);
    cudaStreamWaitEvent(0, eG, 0);
    k_hgemm2<<<dim3(2, 32, 3), 256>>>(cathp, 768, 256, whp + WOFF_K, DD, 0, 0, bk,
                                      kp, DD, (long)NN*DD, (__half*)0, 0, 0, DD);
    cudaStreamWaitEvent(0, eV, 0);
    k_attn<<<NN, 128>>>();
    k_hgemm2<<<dim3(2, 32, 1), 256>>>(atthp, DD, 0, whp + WOFF_O, DD, 0, 0, bo,
                                      xattp, DD, 0, (__half*)0, 0, 0, DD);

    // ---- join + final ----
    cudaStreamWaitEvent(0, eF, 0);
    k_final<<<NN, 256>>>(lng, lnb, out);
}